// round 2
// baseline (speedup 1.0000x reference)
#include <cuda_runtime.h>

// Problem constants
#define BB 4
#define TT 1024
#define EE 1024
#define HH 16
#define HD 64
#define MULT 2
#define SS (TT*MULT)
static constexpr float QSCALE = 0.125f;  // HD^-0.5

// Scratch (allocation-free rule: __device__ globals)
__device__ float g_Q[BB*TT*EE];     // [B,T,E]  scaled q
__device__ float g_K[BB*SS*EE];     // [B,T,2E] == [B,S,E]
__device__ float g_V[BB*SS*EE];
__device__ float g_AO[BB*TT*EE];    // attention output [B,T,E]

// ---------------------------------------------------------------------------
// SGEMM v2: C[m,n] = (sum_k A[m,k]*W[n,k] + bias[n]) * scale
// A:[M,K] rm, W:[N,K] rm. Tile 128x128, k-chunk 16, double-buffered smem.
// 256 threads; thread (ty,tx) owns rows ty*8+i (i<8), cols {tx*4+k, 64+tx*4+k}.
// ---------------------------------------------------------------------------
__global__ __launch_bounds__(256, 2) void sgemm2(
    const float* __restrict__ A, const float* __restrict__ W,
    const float* __restrict__ bias, float* __restrict__ C,
    int N, int K, float scale)
{
    __shared__ float As[2][16*132];
    __shared__ float Bs[2][16*132];

    const int tid = threadIdx.x;
    const int m0 = blockIdx.y * 128;
    const int n0 = blockIdx.x * 128;
    const int ty = tid >> 4, tx = tid & 15;

    const int lr  = tid >> 2;      // 0..63
    const int lc4 = tid & 3;       // 0..3
    const float* Ap  = A + (size_t)(m0 + lr) * K + lc4*4;
    const float* Ap2 = Ap + (size_t)64 * K;
    const float* Wp  = W + (size_t)(n0 + lr) * K + lc4*4;
    const float* Wp2 = Wp + (size_t)64 * K;

    float acc[8][8];
#pragma unroll
    for (int i = 0; i < 8; i++)
#pragma unroll
        for (int j = 0; j < 8; j++) acc[i][j] = 0.f;

    // first chunk -> buffer 0
    {
        float4 a0 = *(const float4*)(Ap);
        float4 a1 = *(const float4*)(Ap2);
        float4 b0 = *(const float4*)(Wp);
        float4 b1 = *(const float4*)(Wp2);
        float* as = As[0]; float* bs = Bs[0];
        as[(lc4*4+0)*132 + lr] = a0.x; as[(lc4*4+1)*132 + lr] = a0.y;
        as[(lc4*4+2)*132 + lr] = a0.z; as[(lc4*4+3)*132 + lr] = a0.w;
        as[(lc4*4+0)*132 + 64+lr] = a1.x; as[(lc4*4+1)*132 + 64+lr] = a1.y;
        as[(lc4*4+2)*132 + 64+lr] = a1.z; as[(lc4*4+3)*132 + 64+lr] = a1.w;
        bs[(lc4*4+0)*132 + lr] = b0.x; bs[(lc4*4+1)*132 + lr] = b0.y;
        bs[(lc4*4+2)*132 + lr] = b0.z; bs[(lc4*4+3)*132 + lr] = b0.w;
        bs[(lc4*4+0)*132 + 64+lr] = b1.x; bs[(lc4*4+1)*132 + 64+lr] = b1.y;
        bs[(lc4*4+2)*132 + 64+lr] = b1.z; bs[(lc4*4+3)*132 + 64+lr] = b1.w;
    }
    __syncthreads();

    const int NC = K >> 4;
    for (int c = 0; c < NC; c++) {
        float4 a0, a1, b0, b1;
        const bool more = (c + 1 < NC);
        if (more) {
            int off = (c + 1) * 16;
            a0 = *(const float4*)(Ap  + off);
            a1 = *(const float4*)(Ap2 + off);
            b0 = *(const float4*)(Wp  + off);
            b1 = *(const float4*)(Wp2 + off);
        }
        const float* as = As[c & 1];
        const float* bs = Bs[c & 1];
#pragma unroll
        for (int kk = 0; kk < 16; kk++) {
            float4 av0 = *(const float4*)&as[kk*132 + ty*8];
            float4 av1 = *(const float4*)&as[kk*132 + ty*8 + 4];
            float4 bv0 = *(const float4*)&bs[kk*132 + tx*4];
            float4 bv1 = *(const float4*)&bs[kk*132 + 64 + tx*4];
            float a[8] = {av0.x,av0.y,av0.z,av0.w, av1.x,av1.y,av1.z,av1.w};
            float b[8] = {bv0.x,bv0.y,bv0.z,bv0.w, bv1.x,bv1.y,bv1.z,bv1.w};
#pragma unroll
            for (int i = 0; i < 8; i++)
#pragma unroll
                for (int j = 0; j < 8; j++)
                    acc[i][j] = fmaf(a[i], b[j], acc[i][j]);
        }
        if (more) {
            float* as2 = (float*)As[(c+1) & 1];
            float* bs2 = (float*)Bs[(c+1) & 1];
            as2[(lc4*4+0)*132 + lr] = a0.x; as2[(lc4*4+1)*132 + lr] = a0.y;
            as2[(lc4*4+2)*132 + lr] = a0.z; as2[(lc4*4+3)*132 + lr] = a0.w;
            as2[(lc4*4+0)*132 + 64+lr] = a1.x; as2[(lc4*4+1)*132 + 64+lr] = a1.y;
            as2[(lc4*4+2)*132 + 64+lr] = a1.z; as2[(lc4*4+3)*132 + 64+lr] = a1.w;
            bs2[(lc4*4+0)*132 + lr] = b0.x; bs2[(lc4*4+1)*132 + lr] = b0.y;
            bs2[(lc4*4+2)*132 + lr] = b0.z; bs2[(lc4*4+3)*132 + lr] = b0.w;
            bs2[(lc4*4+0)*132 + 64+lr] = b1.x; bs2[(lc4*4+1)*132 + 64+lr] = b1.y;
            bs2[(lc4*4+2)*132 + 64+lr] = b1.z; bs2[(lc4*4+3)*132 + 64+lr] = b1.w;
            __syncthreads();
        }
    }

    // epilogue
    float bv[8];
#pragma unroll
    for (int k = 0; k < 4; k++) {
        bv[k]   = bias[n0 + tx*4 + k];
        bv[4+k] = bias[n0 + 64 + tx*4 + k];
    }
#pragma unroll
    for (int i = 0; i < 8; i++) {
        const int m = m0 + ty*8 + i;
        float* crow = C + (size_t)m * N + n0;
        float4 o0, o1;
        o0.x = (acc[i][0] + bv[0]) * scale;
        o0.y = (acc[i][1] + bv[1]) * scale;
        o0.z = (acc[i][2] + bv[2]) * scale;
        o0.w = (acc[i][3] + bv[3]) * scale;
        o1.x = (acc[i][4] + bv[4]) * scale;
        o1.y = (acc[i][5] + bv[5]) * scale;
        o1.z = (acc[i][6] + bv[6]) * scale;
        o1.w = (acc[i][7] + bv[7]) * scale;
        *(float4*)(crow + tx*4)      = o0;
        *(float4*)(crow + 64 + tx*4) = o1;
    }
}

// ---------------------------------------------------------------------------
// Flash attention v2: 128 queries x 128 keys per tile, S in registers.
// grid (T/128, H, B) = (8,16,4); 256 threads; dynamic smem 172032B.
// Thread (ty,tx): S rows ty+16i (i<8), cols tx+16j (j<8); O dims tx*4..tx*4+3.
// Ps buffer double-serves as mask staging (pre-QK) and P (post-softmax).
// ---------------------------------------------------------------------------
__global__ __launch_bounds__(256, 1) void flash_attn2(
    const float* __restrict__ Q, const float* __restrict__ K,
    const float* __restrict__ V, const float* __restrict__ mask,
    float* __restrict__ O)
{
    extern __shared__ float sm[];
    float* Qs = sm;            // [128][68]
    float* Ks = sm + 8704;     // [128][68]
    float* Vs = sm + 17408;    // [128][68]
    float* Ps = sm + 26112;    // [128][132]  mask then P

    const int tid = threadIdx.x;
    const int t0 = blockIdx.x * 128;
    const int h  = blockIdx.y;
    const int b  = blockIdx.z;
    const int ty = tid >> 4, tx = tid & 15;

    // Load Q tile [128][64]
    {
        const float* qb = Q + ((size_t)(b*TT + t0)) * EE + h*HD;
#pragma unroll
        for (int fi = tid; fi < 2048; fi += 256) {
            int r = fi >> 4, c4 = fi & 15;
            *(float4*)&Qs[r*68 + c4*4] = *(const float4*)(qb + (size_t)r*EE + c4*4);
        }
    }

    float Oa[8][4];
#pragma unroll
    for (int i = 0; i < 8; i++)
#pragma unroll
        for (int k = 0; k < 4; k++) Oa[i][k] = 0.f;
    float mrow[8], lrow[8];
#pragma unroll
    for (int i = 0; i < 8; i++) { mrow[i] = -1e30f; lrow[i] = 0.f; }

    const float* kb = K + (size_t)b * SS * EE + h*HD;
    const float* vb = V + (size_t)b * SS * EE + h*HD;
    const float* mb = mask + ((size_t)(b*TT + t0)) * TT;

    for (int st = 0; st < SS/128; st++) {
        const int sb  = st * 128;
        const int s0b = sb & (TT - 1);   // mask col base (s mod T)

        __syncthreads();   // prev-iter smem consumers done
        // K/V tiles
#pragma unroll
        for (int fi = tid; fi < 2048; fi += 256) {
            int r = fi >> 4, c4 = fi & 15;
            *(float4*)&Ks[r*68 + c4*4] = *(const float4*)(kb + (size_t)(sb+r)*EE + c4*4);
            *(float4*)&Vs[r*68 + c4*4] = *(const float4*)(vb + (size_t)(sb+r)*EE + c4*4);
        }
        // mask tile -> Ps (coalesced)
#pragma unroll
        for (int fi = tid; fi < 4096; fi += 256) {
            int r = fi >> 5, c4 = fi & 31;
            *(float4*)&Ps[r*132 + c4*4] = *(const float4*)(mb + (size_t)r*TT + s0b + c4*4);
        }
        __syncthreads();

        // S = Q K^T  (registers)
        float S[8][8];
#pragma unroll
        for (int i = 0; i < 8; i++)
#pragma unroll
            for (int j = 0; j < 8; j++) S[i][j] = 0.f;

#pragma unroll
        for (int d4 = 0; d4 < 16; d4++) {
            float4 qv[8];
#pragma unroll
            for (int i = 0; i < 8; i++)
                qv[i] = *(const float4*)&Qs[(ty + 16*i)*68 + d4*4];
#pragma unroll
            for (int j = 0; j < 8; j++) {
                float4 kv = *(const float4*)&Ks[(tx + 16*j)*68 + d4*4];
#pragma unroll
                for (int i = 0; i < 8; i++)
                    S[i][j] = fmaf(qv[i].x, kv.x,
                               fmaf(qv[i].y, kv.y,
                               fmaf(qv[i].z, kv.z,
                               fmaf(qv[i].w, kv.w, S[i][j]))));
            }
        }

        // + mask, online softmax (row groups = 16 lanes sharing ty)
#pragma unroll
        for (int i = 0; i < 8; i++) {
            const int rbase = (ty + 16*i) * 132;
            float lm = -1e30f;
#pragma unroll
            for (int j = 0; j < 8; j++) {
                S[i][j] += Ps[rbase + tx + 16*j];
                lm = fmaxf(lm, S[i][j]);
            }
            lm = fmaxf(lm, __shfl_xor_sync(0xffffffffu, lm, 1));
            lm = fmaxf(lm, __shfl_xor_sync(0xffffffffu, lm, 2));
            lm = fmaxf(lm, __shfl_xor_sync(0xffffffffu, lm, 4));
            lm = fmaxf(lm, __shfl_xor_sync(0xffffffffu, lm, 8));
            float mn = fmaxf(mrow[i], lm);
            float a  = __expf(mrow[i] - mn);
            mrow[i] = mn;
            float ls = 0.f;
#pragma unroll
            for (int j = 0; j < 8; j++) {
                float p = __expf(S[i][j] - mn);
                S[i][j] = p;
                ls += p;
            }
            ls += __shfl_xor_sync(0xffffffffu, ls, 1);
            ls += __shfl_xor_sync(0xffffffffu, ls, 2);
            ls += __shfl_xor_sync(0xffffffffu, ls, 4);
            ls += __shfl_xor_sync(0xffffffffu, ls, 8);
            lrow[i] = lrow[i] * a + ls;
#pragma unroll
            for (int k = 0; k < 4; k++) Oa[i][k] *= a;
#pragma unroll
            for (int j = 0; j < 8; j++) Ps[rbase + tx + 16*j] = S[i][j];
        }
        __syncthreads();

        // O += P V
#pragma unroll
        for (int s4 = 0; s4 < 32; s4++) {
            float4 vv0 = *(const float4*)&Vs[(s4*4+0)*68 + tx*4];
            float4 vv1 = *(const float4*)&Vs[(s4*4+1)*68 + tx*4];
            float4 vv2 = *(const float4*)&Vs[(s4*4+2)*68 + tx*4];
            float4 vv3 = *(const float4*)&Vs[(s4*4+3)*68 + tx*4];
#pragma unroll
            for (int i = 0; i < 8; i++) {
                float4 pv = *(const float4*)&Ps[(ty + 16*i)*132 + s4*4];
                Oa[i][0] = fmaf(pv.x, vv0.x, Oa[i][0]);
                Oa[i][1] = fmaf(pv.x, vv0.y, Oa[i][1]);
                Oa[i][2] = fmaf(pv.x, vv0.z, Oa[i][2]);
                Oa[i][3] = fmaf(pv.x, vv0.w, Oa[i][3]);
                Oa[i][0] = fmaf(pv.y, vv1.x, Oa[i][0]);
                Oa[i][1] = fmaf(pv.y, vv1.y, Oa[i][1]);
                Oa[i][2] = fmaf(pv.y, vv1.z, Oa[i][2]);
                Oa[i][3] = fmaf(pv.y, vv1.w, Oa[i][3]);
                Oa[i][0] = fmaf(pv.z, vv2.x, Oa[i][0]);
                Oa[i][1] = fmaf(pv.z, vv2.y, Oa[i][1]);
                Oa[i][2] = fmaf(pv.z, vv2.z, Oa[i][2]);
                Oa[i][3] = fmaf(pv.z, vv2.w, Oa[i][3]);
                Oa[i][0] = fmaf(pv.w, vv3.x, Oa[i][0]);
                Oa[i][1] = fmaf(pv.w, vv3.y, Oa[i][1]);
                Oa[i][2] = fmaf(pv.w, vv3.z, Oa[i][2]);
                Oa[i][3] = fmaf(pv.w, vv3.w, Oa[i][3]);
            }
        }
    }

    // write out: O[b, t0+r, h*HD + tx*4..]
    {
        float* ob = O + ((size_t)(b*TT + t0)) * EE + h*HD;
#pragma unroll
        for (int i = 0; i < 8; i++) {
            int r = ty + 16*i;
            float inv = 1.f / lrow[i];
            float4 o;
            o.x = Oa[i][0] * inv;
            o.y = Oa[i][1] * inv;
            o.z = Oa[i][2] * inv;
            o.w = Oa[i][3] * inv;
            *(float4*)(ob + (size_t)r*EE + tx*4) = o;
        }
    }
}

// ---------------------------------------------------------------------------
extern "C" void kernel_launch(void* const* d_in, const int* in_sizes, int n_in,
                              void* d_out, int out_size) {
    const float* x    = (const float*)d_in[0];
    const float* mask = (const float*)d_in[1];
    const float* Wq   = (const float*)d_in[2];
    const float* bq   = (const float*)d_in[3];
    const float* Wk   = (const float*)d_in[4];
    const float* bk   = (const float*)d_in[5];
    const float* Wv   = (const float*)d_in[6];
    const float* bv   = (const float*)d_in[7];
    const float* Wo   = (const float*)d_in[8];
    const float* bo   = (const float*)d_in[9];
    float* out = (float*)d_out;

    float *Qp, *Kp, *Vp, *AOp;
    cudaGetSymbolAddress((void**)&Qp, g_Q);
    cudaGetSymbolAddress((void**)&Kp, g_K);
    cudaGetSymbolAddress((void**)&Vp, g_V);
    cudaGetSymbolAddress((void**)&AOp, g_AO);

    static bool attr_done = false;
    if (!attr_done) {
        cudaFuncSetAttribute(flash_attn2,
                             cudaFuncAttributeMaxDynamicSharedMemorySize, 172032);
        attr_done = true;
    }

    dim3 blk(256);
    // Q = (x Wq^T + bq) * scale     [4096 x 1024]
    sgemm2<<<dim3(EE/128, (BB*TT)/128), blk>>>(x, Wq, bq, Qp, EE, EE, QSCALE);
    // K = x Wk^T + bk               [4096 x 2048]
    sgemm2<<<dim3((MULT*EE)/128, (BB*TT)/128), blk>>>(x, Wk, bk, Kp, MULT*EE, EE, 1.f);
    // V = x Wv^T + bv               [4096 x 2048]
    sgemm2<<<dim3((MULT*EE)/128, (BB*TT)/128), blk>>>(x, Wv, bv, Vp, MULT*EE, EE, 1.f);
    // flash attention -> g_AO [B,T,E]
    flash_attn2<<<dim3(TT/128, HH, BB), blk, 172032>>>(Qp, Kp, Vp, mask, AOp);
    // out = AO Wo^T + bo            [4096 x 1024]
    sgemm2<<<dim3(EE/128, (BB*TT)/128), blk>>>(AOp, Wo, bo, out, EE, EE, 1.f);
}

// round 3
// speedup vs baseline: 1.3655x; 1.3655x over previous
#include <cuda_runtime.h>
#include <cuda_bf16.h>
#include <mma.h>

using namespace nvcuda;

// Problem constants
#define BB 4
#define TT 1024
#define EE 1024
#define HH 16
#define HD 64
#define MULT 2
#define SS (TT*MULT)
static constexpr float QSCALE = 0.125f;  // HD^-0.5

// Scratch (allocation-free rule: __device__ globals)
__device__ float g_Q[BB*TT*EE];     // [B,T,E]  scaled q
__device__ float g_K[BB*SS*EE];     // [B,T,2E] == [B,S,E]
__device__ float g_V[BB*SS*EE];
__device__ float g_AO[BB*TT*EE];    // attention output [B,T,E]

// ---------------------------------------------------------------------------
// Tensor-core SGEMM (bf16 3-term split, fp32 accumulate):
//   C[m,n] = (sum_k A[m,k]*W[n,k] + bias[n]) * scale
// A:[M,K] rm, W:[N,K] rm. Tile 128x128, k-chunk 32, double-buffered smem.
// 256 threads = 8 warps in 2x4 grid; warp owns 64x32 (4x2 m16n16k16 frags).
// Split: a = hi + lo (both bf16); A.W ~= Ah.Wh + Ah.Wl + Al.Wh  (~1e-5 rel).
// ---------------------------------------------------------------------------
#define LDT 40                      // smem row stride (bf16 elems), 32 + 8 pad
#define MAT (128*LDT)               // elems per staged matrix
#define SG_SMEM (2*4*MAT*2)         // bytes: 2 bufs x {Ah,Al,Wh,Wl} x bf16

__global__ __launch_bounds__(256) void sgemm_tc(
    const float* __restrict__ A, const float* __restrict__ W,
    const float* __restrict__ bias, float* __restrict__ C,
    int N, int K, float scale)
{
    extern __shared__ __nv_bfloat16 sm_tc[];

    const int tid = threadIdx.x;
    const int m0 = blockIdx.y * 128;
    const int n0 = blockIdx.x * 128;
    const int wid = tid >> 5;
    const int wm = wid >> 2;        // 0..1  (64-row band)
    const int wn = wid & 3;         // 0..3  (32-col band)

    const float* Abase = A + (size_t)m0 * K;
    const float* Wbase = W + (size_t)n0 * K;

    wmma::fragment<wmma::accumulator, 16, 16, 16, float> acc[4][2];
#pragma unroll
    for (int i = 0; i < 4; i++)
#pragma unroll
        for (int j = 0; j < 2; j++) wmma::fill_fragment(acc[i][j], 0.f);

    // per-thread load slots: 4 float4 of A + 4 float4 of W per chunk
    // fi = tid + t*256 in [0,1024): r = fi>>3 (row 0..127), c4 = (fi&7)*4
    const int lr  = tid >> 3;            // base row (stride 32 over t)
    const int lc4 = (tid & 7) * 4;       // col within 32-chunk

    // ---- load chunk 0 into buffer 0 ----
    {
        __nv_bfloat16* sAh = sm_tc;
        __nv_bfloat16* sAl = sm_tc + MAT;
        __nv_bfloat16* sWh = sm_tc + 2*MAT;
        __nv_bfloat16* sWl = sm_tc + 3*MAT;
#pragma unroll
        for (int t = 0; t < 4; t++) {
            int r = lr + t*32;
            float4 av = *(const float4*)(Abase + (size_t)r*K + lc4);
            float4 wv = *(const float4*)(Wbase + (size_t)r*K + lc4);
            int o = r*LDT + lc4;
#define CVT_ST(H, L, idx, x) { __nv_bfloat16 _h = __float2bfloat16(x); \
            H[idx] = _h; L[idx] = __float2bfloat16((x) - __bfloat162float(_h)); }
            CVT_ST(sAh, sAl, o+0, av.x); CVT_ST(sAh, sAl, o+1, av.y);
            CVT_ST(sAh, sAl, o+2, av.z); CVT_ST(sAh, sAl, o+3, av.w);
            CVT_ST(sWh, sWl, o+0, wv.x); CVT_ST(sWh, sWl, o+1, wv.y);
            CVT_ST(sWh, sWl, o+2, wv.z); CVT_ST(sWh, sWl, o+3, wv.w);
        }
    }
    __syncthreads();

    const int NC = K >> 5;   // chunks of 32
    for (int c = 0; c < NC; c++) {
        const bool more = (c + 1 < NC);
        // prefetch next chunk into regs (overlaps with MMA below)
        float4 pa[4], pw[4];
        if (more) {
            int kc = (c + 1) * 32;
#pragma unroll
            for (int t = 0; t < 4; t++) {
                int r = lr + t*32;
                pa[t] = *(const float4*)(Abase + (size_t)r*K + kc + lc4);
                pw[t] = *(const float4*)(Wbase + (size_t)r*K + kc + lc4);
            }
        }

        // compute on buffer (c & 1)
        {
            const __nv_bfloat16* buf = sm_tc + (size_t)(c & 1) * 4 * MAT;
            const __nv_bfloat16* sAh = buf;
            const __nv_bfloat16* sAl = buf + MAT;
            const __nv_bfloat16* sWh = buf + 2*MAT;
            const __nv_bfloat16* sWl = buf + 3*MAT;

#pragma unroll
            for (int kf = 0; kf < 2; kf++) {
                const int k0 = kf * 16;
                wmma::fragment<wmma::matrix_a, 16,16,16, __nv_bfloat16, wmma::row_major> ah[4], al[4];
                wmma::fragment<wmma::matrix_b, 16,16,16, __nv_bfloat16, wmma::col_major> bh[2], bl[2];
#pragma unroll
                for (int i = 0; i < 4; i++) {
                    int rbase = (wm*64 + i*16) * LDT + k0;
                    wmma::load_matrix_sync(ah[i], sAh + rbase, LDT);
                    wmma::load_matrix_sync(al[i], sAl + rbase, LDT);
                }
#pragma unroll
                for (int j = 0; j < 2; j++) {
                    int nbase = (wn*32 + j*16) * LDT + k0;
                    wmma::load_matrix_sync(bh[j], sWh + nbase, LDT);
                    wmma::load_matrix_sync(bl[j], sWl + nbase, LDT);
                }
#pragma unroll
                for (int i = 0; i < 4; i++)
#pragma unroll
                    for (int j = 0; j < 2; j++) {
                        wmma::mma_sync(acc[i][j], ah[i], bh[j], acc[i][j]);
                        wmma::mma_sync(acc[i][j], ah[i], bl[j], acc[i][j]);
                        wmma::mma_sync(acc[i][j], al[i], bh[j], acc[i][j]);
                    }
            }
        }

        if (more) {
            __nv_bfloat16* buf = sm_tc + (size_t)((c + 1) & 1) * 4 * MAT;
            __nv_bfloat16* sAh = buf;
            __nv_bfloat16* sAl = buf + MAT;
            __nv_bfloat16* sWh = buf + 2*MAT;
            __nv_bfloat16* sWl = buf + 3*MAT;
#pragma unroll
            for (int t = 0; t < 4; t++) {
                int r = lr + t*32;
                int o = r*LDT + lc4;
                CVT_ST(sAh, sAl, o+0, pa[t].x); CVT_ST(sAh, sAl, o+1, pa[t].y);
                CVT_ST(sAh, sAl, o+2, pa[t].z); CVT_ST(sAh, sAl, o+3, pa[t].w);
                CVT_ST(sWh, sWl, o+0, pw[t].x); CVT_ST(sWh, sWl, o+1, pw[t].y);
                CVT_ST(sWh, sWl, o+2, pw[t].z); CVT_ST(sWh, sWl, o+3, pw[t].w);
            }
        }
        __syncthreads();
    }

    // ---- epilogue: stage each frag through smem, add bias, scale, store ----
    float* ep = (float*)sm_tc + wid * (16*20);
    const int lane = tid & 31;
#pragma unroll
    for (int i = 0; i < 4; i++) {
#pragma unroll
        for (int j = 0; j < 2; j++) {
            wmma::store_matrix_sync(ep, acc[i][j], 20, wmma::mem_row_major);
            __syncwarp();
#pragma unroll
            for (int e = 0; e < 8; e++) {
                int idx = lane * 8 + e;
                int r = idx >> 4, cc = idx & 15;
                int m = m0 + wm*64 + i*16 + r;
                int n = n0 + wn*32 + j*16 + cc;
                C[(size_t)m * N + n] = (ep[r*20 + cc] + bias[n]) * scale;
            }
            __syncwarp();
        }
    }
}

// ---------------------------------------------------------------------------
// Flash attention (R1 proven version), fp32, online softmax.
// grid: (T/64, H, B), 256 threads.
// ---------------------------------------------------------------------------
__global__ __launch_bounds__(256) void flash_attn(
    const float* __restrict__ Q, const float* __restrict__ K,
    const float* __restrict__ V, const float* __restrict__ mask,
    float* __restrict__ O)
{
    __shared__ float Qs[64][64];
    __shared__ float Ks[32][68];
    __shared__ float Vs[32][68];
    __shared__ float Ssm[64][36];
    __shared__ float alpha_s[64];
    __shared__ float l_s[64];

    const int tid = threadIdx.x;
    const int t0 = blockIdx.x * 64;
    const int h  = blockIdx.y;
    const int b  = blockIdx.z;

    const int uy = tid >> 4, ux = tid & 15;
    const int sy = tid >> 3, sx = tid & 7;
    const int rrow = tid >> 2, rp = tid & 3;

    {
        const float* qbase = Q + ((size_t)(b*TT + t0)) * EE + h*HD;
        for (int fi = tid; fi < 1024; fi += 256) {
            int qi = fi >> 4, dg = (fi & 15) << 2;
            *(float4*)&Qs[qi][dg] = *(const float4*)(qbase + (size_t)qi*EE + dg);
        }
    }

    float acc[4][4];
#pragma unroll
    for (int i = 0; i < 4; i++)
#pragma unroll
        for (int j = 0; j < 4; j++) acc[i][j] = 0.f;
    float m_old = -1e30f, lsum_run = 0.f;

    const float* kb = K + (size_t)b * SS * EE + h*HD;
    const float* vb = V + (size_t)b * SS * EE + h*HD;
    const float* mb = mask + ((size_t)(b*TT + t0)) * TT;

    for (int st = 0; st < SS/32; st++) {
        const int s_base = st * 32;
        const int s0_base = s_base & (TT - 1);

        for (int fi = tid; fi < 512; fi += 256) {
            int sj = fi >> 4, dg = (fi & 15) << 2;
            *(float4*)&Ks[sj][dg] = *(const float4*)(kb + (size_t)(s_base+sj)*EE + dg);
            *(float4*)&Vs[sj][dg] = *(const float4*)(vb + (size_t)(s_base+sj)*EE + dg);
        }
        for (int fi = tid; fi < 512; fi += 256) {
            int qi = fi >> 3, sg = (fi & 7) << 2;
            float4 mv = *(const float4*)(mb + (size_t)qi*TT + s0_base + sg);
            Ssm[qi][sg+0] = mv.x; Ssm[qi][sg+1] = mv.y;
            Ssm[qi][sg+2] = mv.z; Ssm[qi][sg+3] = mv.w;
        }
        __syncthreads();

        {
            float qk[2][4];
#pragma unroll
            for (int i = 0; i < 2; i++)
#pragma unroll
                for (int j = 0; j < 4; j++) qk[i][j] = 0.f;
#pragma unroll
            for (int d4 = 0; d4 < 16; d4++) {
                float4 q0 = *(const float4*)&Qs[sy*2+0][d4*4];
                float4 q1 = *(const float4*)&Qs[sy*2+1][d4*4];
                float4 k0 = *(const float4*)&Ks[sx*4+0][d4*4];
                float4 k1 = *(const float4*)&Ks[sx*4+1][d4*4];
                float4 k2 = *(const float4*)&Ks[sx*4+2][d4*4];
                float4 k3 = *(const float4*)&Ks[sx*4+3][d4*4];
#define DOT4(ac, qv, kv) ac = fmaf(qv.x,kv.x, fmaf(qv.y,kv.y, fmaf(qv.z,kv.z, fmaf(qv.w,kv.w, ac))))
                DOT4(qk[0][0], q0, k0); DOT4(qk[0][1], q0, k1);
                DOT4(qk[0][2], q0, k2); DOT4(qk[0][3], q0, k3);
                DOT4(qk[1][0], q1, k0); DOT4(qk[1][1], q1, k1);
                DOT4(qk[1][2], q1, k2); DOT4(qk[1][3], q1, k3);
#undef DOT4
            }
#pragma unroll
            for (int i = 0; i < 2; i++)
#pragma unroll
                for (int j = 0; j < 4; j++)
                    Ssm[sy*2+i][sx*4+j] += qk[i][j];
        }
        __syncthreads();

        {
            float lm = -1e30f;
#pragma unroll
            for (int j = 0; j < 8; j++) lm = fmaxf(lm, Ssm[rrow][rp*8+j]);
            lm = fmaxf(lm, __shfl_xor_sync(0xffffffffu, lm, 1));
            lm = fmaxf(lm, __shfl_xor_sync(0xffffffffu, lm, 2));
            float m_new = fmaxf(m_old, lm);
            float a = __expf(m_old - m_new);
            float ls = 0.f;
#pragma unroll
            for (int j = 0; j < 8; j++) {
                float p = __expf(Ssm[rrow][rp*8+j] - m_new);
                Ssm[rrow][rp*8+j] = p;
                ls += p;
            }
            ls += __shfl_xor_sync(0xffffffffu, ls, 1);
            ls += __shfl_xor_sync(0xffffffffu, ls, 2);
            lsum_run = lsum_run * a + ls;
            m_old = m_new;
            if (rp == 0) alpha_s[rrow] = a;
        }
        __syncthreads();

        {
#pragma unroll
            for (int i = 0; i < 4; i++) {
                float a = alpha_s[uy*4+i];
#pragma unroll
                for (int j = 0; j < 4; j++) acc[i][j] *= a;
            }
#pragma unroll
            for (int s = 0; s < 32; s++) {
                float4 vv = *(const float4*)&Vs[s][ux*4];
                float p0 = Ssm[uy*4+0][s];
                float p1 = Ssm[uy*4+1][s];
                float p2 = Ssm[uy*4+2][s];
                float p3 = Ssm[uy*4+3][s];
                acc[0][0] = fmaf(p0, vv.x, acc[0][0]);
                acc[0][1] = fmaf(p0, vv.y, acc[0][1]);
                acc[0][2] = fmaf(p0, vv.z, acc[0][2]);
                acc[0][3] = fmaf(p0, vv.w, acc[0][3]);
                acc[1][0] = fmaf(p1, vv.x, acc[1][0]);
                acc[1][1] = fmaf(p1, vv.y, acc[1][1]);
                acc[1][2] = fmaf(p1, vv.z, acc[1][2]);
                acc[1][3] = fmaf(p1, vv.w, acc[1][3]);
                acc[2][0] = fmaf(p2, vv.x, acc[2][0]);
                acc[2][1] = fmaf(p2, vv.y, acc[2][1]);
                acc[2][2] = fmaf(p2, vv.z, acc[2][2]);
                acc[2][3] = fmaf(p2, vv.w, acc[2][3]);
                acc[3][0] = fmaf(p3, vv.x, acc[3][0]);
                acc[3][1] = fmaf(p3, vv.y, acc[3][1]);
                acc[3][2] = fmaf(p3, vv.z, acc[3][2]);
                acc[3][3] = fmaf(p3, vv.w, acc[3][3]);
            }
        }
        __syncthreads();
    }

    if (rp == 0) l_s[rrow] = lsum_run;
    __syncthreads();

    {
        float* ob = O + ((size_t)(b*TT + t0)) * EE + h*HD;
#pragma unroll
        for (int i = 0; i < 4; i++) {
            int q = uy*4 + i;
            float inv = 1.f / l_s[q];
            float4 o;
            o.x = acc[i][0] * inv;
            o.y = acc[i][1] * inv;
            o.z = acc[i][2] * inv;
            o.w = acc[i][3] * inv;
            *(float4*)(ob + (size_t)q*EE + ux*4) = o;
        }
    }
}

// ---------------------------------------------------------------------------
extern "C" void kernel_launch(void* const* d_in, const int* in_sizes, int n_in,
                              void* d_out, int out_size) {
    const float* x    = (const float*)d_in[0];
    const float* mask = (const float*)d_in[1];
    const float* Wq   = (const float*)d_in[2];
    const float* bq   = (const float*)d_in[3];
    const float* Wk   = (const float*)d_in[4];
    const float* bk   = (const float*)d_in[5];
    const float* Wv   = (const float*)d_in[6];
    const float* bv   = (const float*)d_in[7];
    const float* Wo   = (const float*)d_in[8];
    const float* bo   = (const float*)d_in[9];
    float* out = (float*)d_out;

    float *Qp, *Kp, *Vp, *AOp;
    cudaGetSymbolAddress((void**)&Qp, g_Q);
    cudaGetSymbolAddress((void**)&Kp, g_K);
    cudaGetSymbolAddress((void**)&Vp, g_V);
    cudaGetSymbolAddress((void**)&AOp, g_AO);

    static bool attr_done = false;
    if (!attr_done) {
        cudaFuncSetAttribute(sgemm_tc,
                             cudaFuncAttributeMaxDynamicSharedMemorySize, SG_SMEM);
        attr_done = true;
    }

    dim3 blk(256);
    // Q = (x Wq^T + bq) * scale     [4096 x 1024]
    sgemm_tc<<<dim3(EE/128, (BB*TT)/128), blk, SG_SMEM>>>(x, Wq, bq, Qp, EE, EE, QSCALE);
    // K = x Wk^T + bk               [4096 x 2048]
    sgemm_tc<<<dim3((MULT*EE)/128, (BB*TT)/128), blk, SG_SMEM>>>(x, Wk, bk, Kp, MULT*EE, EE, 1.f);
    // V = x Wv^T + bv               [4096 x 2048]
    sgemm_tc<<<dim3((MULT*EE)/128, (BB*TT)/128), blk, SG_SMEM>>>(x, Wv, bv, Vp, MULT*EE, EE, 1.f);
    // flash attention -> g_AO [B,T,E]
    flash_attn<<<dim3(TT/64, HH, BB), blk>>>(Qp, Kp, Vp, mask, AOp);
    // out = AO Wo^T + bo            [4096 x 1024]
    sgemm_tc<<<dim3(EE/128, (BB*TT)/128), blk, SG_SMEM>>>(AOp, Wo, bo, out, EE, EE, 1.f);
}

// round 5
// speedup vs baseline: 2.8788x; 2.1083x over previous
#include <cuda_runtime.h>
#include <cuda_bf16.h>
#include <mma.h>

using namespace nvcuda;

// Problem constants
#define BB 4
#define TT 1024
#define EE 1024
#define HH 16
#define HD 64
#define MULT 2
#define SS (TT*MULT)
static constexpr float QSCALE = 0.125f;  // HD^-0.5

// Scratch (allocation-free rule: __device__ globals)
__device__ __nv_bfloat16 g_Qh[BB*TT*EE];   // [B,T,E] bf16 hi (scaled)
__device__ __nv_bfloat16 g_Ql[BB*TT*EE];   // lo
__device__ __nv_bfloat16 g_Kh[BB*SS*EE];   // [B,S,E] bf16 hi
__device__ __nv_bfloat16 g_Kl[BB*SS*EE];
__device__ __nv_bfloat16 g_Vh[BB*SS*EE];   // V hi
__device__ __nv_bfloat16 g_Vl[BB*SS*EE];   // V lo
__device__ float g_AO[BB*TT*EE];           // attention output fp32 [B,T,E]

// ---------------------------------------------------------------------------
// Tensor-core SGEMM (bf16 3-term split in, fp32 accum).
// OMODE 0: fp32 C out. 1: bf16 split (Ch,Cl).
// ---------------------------------------------------------------------------
#define LDT 40
#define MAT (128*LDT)
#define SG_SMEM (2*4*MAT*2)

template<int OMODE>
__global__ __launch_bounds__(256) void sgemm_tc(
    const float* __restrict__ A, const float* __restrict__ W,
    const float* __restrict__ bias, float* __restrict__ C,
    __nv_bfloat16* __restrict__ Ch, __nv_bfloat16* __restrict__ Cl,
    int N, int K, float scale)
{
    extern __shared__ __nv_bfloat16 sm_tc[];

    const int tid = threadIdx.x;
    const int m0 = blockIdx.y * 128;
    const int n0 = blockIdx.x * 128;
    const int wid = tid >> 5;
    const int wm = wid >> 2;
    const int wn = wid & 3;

    const float* Abase = A + (size_t)m0 * K;
    const float* Wbase = W + (size_t)n0 * K;

    wmma::fragment<wmma::accumulator, 16, 16, 16, float> acc[4][2];
#pragma unroll
    for (int i = 0; i < 4; i++)
#pragma unroll
        for (int j = 0; j < 2; j++) wmma::fill_fragment(acc[i][j], 0.f);

    const int lr  = tid >> 3;
    const int lc4 = (tid & 7) * 4;

#define CVT_ST(H, L, idx, x) { __nv_bfloat16 _h = __float2bfloat16(x); \
        H[idx] = _h; L[idx] = __float2bfloat16((x) - __bfloat162float(_h)); }

    {
        __nv_bfloat16* sAh = sm_tc;
        __nv_bfloat16* sAl = sm_tc + MAT;
        __nv_bfloat16* sWh = sm_tc + 2*MAT;
        __nv_bfloat16* sWl = sm_tc + 3*MAT;
#pragma unroll
        for (int t = 0; t < 4; t++) {
            int r = lr + t*32;
            float4 av = *(const float4*)(Abase + (size_t)r*K + lc4);
            float4 wv = *(const float4*)(Wbase + (size_t)r*K + lc4);
            int o = r*LDT + lc4;
            CVT_ST(sAh, sAl, o+0, av.x); CVT_ST(sAh, sAl, o+1, av.y);
            CVT_ST(sAh, sAl, o+2, av.z); CVT_ST(sAh, sAl, o+3, av.w);
            CVT_ST(sWh, sWl, o+0, wv.x); CVT_ST(sWh, sWl, o+1, wv.y);
            CVT_ST(sWh, sWl, o+2, wv.z); CVT_ST(sWh, sWl, o+3, wv.w);
        }
    }
    __syncthreads();

    const int NC = K >> 5;
    for (int c = 0; c < NC; c++) {
        const bool more = (c + 1 < NC);
        float4 pa[4], pw[4];
        if (more) {
            int kc = (c + 1) * 32;
#pragma unroll
            for (int t = 0; t < 4; t++) {
                int r = lr + t*32;
                pa[t] = *(const float4*)(Abase + (size_t)r*K + kc + lc4);
                pw[t] = *(const float4*)(Wbase + (size_t)r*K + kc + lc4);
            }
        }
        {
            const __nv_bfloat16* buf = sm_tc + (size_t)(c & 1) * 4 * MAT;
            const __nv_bfloat16* sAh = buf;
            const __nv_bfloat16* sAl = buf + MAT;
            const __nv_bfloat16* sWh = buf + 2*MAT;
            const __nv_bfloat16* sWl = buf + 3*MAT;
#pragma unroll
            for (int kf = 0; kf < 2; kf++) {
                const int k0 = kf * 16;
                wmma::fragment<wmma::matrix_a, 16,16,16, __nv_bfloat16, wmma::row_major> ah[4], al[4];
                wmma::fragment<wmma::matrix_b, 16,16,16, __nv_bfloat16, wmma::col_major> bh[2], bl[2];
#pragma unroll
                for (int i = 0; i < 4; i++) {
                    int rbase = (wm*64 + i*16) * LDT + k0;
                    wmma::load_matrix_sync(ah[i], sAh + rbase, LDT);
                    wmma::load_matrix_sync(al[i], sAl + rbase, LDT);
                }
#pragma unroll
                for (int j = 0; j < 2; j++) {
                    int nbase = (wn*32 + j*16) * LDT + k0;
                    wmma::load_matrix_sync(bh[j], sWh + nbase, LDT);
                    wmma::load_matrix_sync(bl[j], sWl + nbase, LDT);
                }
#pragma unroll
                for (int i = 0; i < 4; i++)
#pragma unroll
                    for (int j = 0; j < 2; j++) {
                        wmma::mma_sync(acc[i][j], ah[i], bh[j], acc[i][j]);
                        wmma::mma_sync(acc[i][j], ah[i], bl[j], acc[i][j]);
                        wmma::mma_sync(acc[i][j], al[i], bh[j], acc[i][j]);
                    }
            }
        }
        if (more) {
            __nv_bfloat16* buf = sm_tc + (size_t)((c + 1) & 1) * 4 * MAT;
            __nv_bfloat16* sAh = buf;
            __nv_bfloat16* sAl = buf + MAT;
            __nv_bfloat16* sWh = buf + 2*MAT;
            __nv_bfloat16* sWl = buf + 3*MAT;
#pragma unroll
            for (int t = 0; t < 4; t++) {
                int r = lr + t*32;
                int o = r*LDT + lc4;
                CVT_ST(sAh, sAl, o+0, pa[t].x); CVT_ST(sAh, sAl, o+1, pa[t].y);
                CVT_ST(sAh, sAl, o+2, pa[t].z); CVT_ST(sAh, sAl, o+3, pa[t].w);
                CVT_ST(sWh, sWl, o+0, pw[t].x); CVT_ST(sWh, sWl, o+1, pw[t].y);
                CVT_ST(sWh, sWl, o+2, pw[t].z); CVT_ST(sWh, sWl, o+3, pw[t].w);
            }
        }
        __syncthreads();
    }

    // epilogue
    float* ep = (float*)sm_tc + wid * (16*20);
    const int lane = tid & 31;
#pragma unroll
    for (int i = 0; i < 4; i++) {
#pragma unroll
        for (int j = 0; j < 2; j++) {
            wmma::store_matrix_sync(ep, acc[i][j], 20, wmma::mem_row_major);
            __syncwarp();
#pragma unroll
            for (int e = 0; e < 8; e++) {
                int idx = lane * 8 + e;
                int r = idx >> 4, cc = idx & 15;
                int m = m0 + wm*64 + i*16 + r;
                int n = n0 + wn*32 + j*16 + cc;
                float v = (ep[r*20 + cc] + bias[n]) * scale;
                if (OMODE == 0) {
                    C[(size_t)m * N + n] = v;
                } else {
                    __nv_bfloat16 hh = __float2bfloat16(v);
                    Ch[(size_t)m * N + n] = hh;
                    Cl[(size_t)m * N + n] = __float2bfloat16(v - __bfloat162float(hh));
                }
            }
            __syncwarp();
        }
    }
}

// ---------------------------------------------------------------------------
// Tensor-core flash attention, no-max-shift softmax (scores are O(1));
// exp sums in fp32, divide at end. O accumulates in wmma fragments.
// grid (T/64, H, B); 256 threads = 8 warps (wm 0..1, wn 0..3).
// QK: 3-term bf16 split. PV: 3-term bf16 split (Ph,Pl x Vh,Vl).
// ---------------------------------------------------------------------------
#define LDQ 72
#define LDK 72
#define LDSF 136
// smem byte offsets
#define OFF_QH 0
#define OFF_QL 9216
#define OFF_KH 18432
#define OFF_KL 36864
#define OFF_VH 55296
#define OFF_VL 73728
#define OFF_S  92160            // 64x136 fp32 = 34816; aliased by Ph/Pl and sO
#define OFF_PH 92160            // 64x136 bf16 = 17408
#define OFF_PL 109568           // 64x136 bf16 = 17408
#define OFF_L  126976           // 64 floats
#define FL_SMEM 127232

__global__ __launch_bounds__(256) void flash_tc(
    const __nv_bfloat16* __restrict__ Qh, const __nv_bfloat16* __restrict__ Ql,
    const __nv_bfloat16* __restrict__ Kh, const __nv_bfloat16* __restrict__ Kl,
    const __nv_bfloat16* __restrict__ Vh, const __nv_bfloat16* __restrict__ Vl,
    const float* __restrict__ mask, float* __restrict__ O)
{
    extern __shared__ char smraw[];
    __nv_bfloat16* sQh = (__nv_bfloat16*)(smraw + OFF_QH);  // 64x72
    __nv_bfloat16* sQl = (__nv_bfloat16*)(smraw + OFF_QL);
    __nv_bfloat16* sKh = (__nv_bfloat16*)(smraw + OFF_KH);  // 128x72
    __nv_bfloat16* sKl = (__nv_bfloat16*)(smraw + OFF_KL);
    __nv_bfloat16* sVh = (__nv_bfloat16*)(smraw + OFF_VH);  // 128x72
    __nv_bfloat16* sVl = (__nv_bfloat16*)(smraw + OFF_VL);
    float*         sS  = (float*)(smraw + OFF_S);           // 64x136 fp32
    __nv_bfloat16* sPh = (__nv_bfloat16*)(smraw + OFF_PH);  // alias
    __nv_bfloat16* sPl = (__nv_bfloat16*)(smraw + OFF_PL);  // alias
    float*         sO  = (float*)(smraw + OFF_S);           // alias 64x72 fp32
    float*         sL  = (float*)(smraw + OFF_L);

    const int tid = threadIdx.x;
    const int t0 = blockIdx.x * 64;
    const int h  = blockIdx.y;
    const int b  = blockIdx.z;
    const int wid = tid >> 5;
    const int wm = wid >> 2;        // 0..1
    const int wn = wid & 3;         // 0..3

    {
        const __nv_bfloat16* qh = Qh + ((size_t)(b*TT + t0)) * EE + h*HD;
        const __nv_bfloat16* ql = Ql + ((size_t)(b*TT + t0)) * EE + h*HD;
#pragma unroll
        for (int i = tid; i < 1024; i += 256) {
            int r = i >> 4, c = (i & 15) * 4;
            *(uint2*)&sQh[r*LDQ + c] = *(const uint2*)(qh + (size_t)r*EE + c);
            *(uint2*)&sQl[r*LDQ + c] = *(const uint2*)(ql + (size_t)r*EE + c);
        }
        if (tid < 64) sL[tid] = 0.f;
    }

    wmma::fragment<wmma::accumulator, 16, 16, 16, float> oacc[2];
    wmma::fill_fragment(oacc[0], 0.f);
    wmma::fill_fragment(oacc[1], 0.f);

    const int srow = tid >> 2;          // softmax row 0..63
    const int scb  = (tid & 3) * 32;    // col base

    const __nv_bfloat16* kbh = Kh + (size_t)b * SS * EE + h*HD;
    const __nv_bfloat16* kbl = Kl + (size_t)b * SS * EE + h*HD;
    const __nv_bfloat16* vbh = Vh + (size_t)b * SS * EE + h*HD;
    const __nv_bfloat16* vbl = Vl + (size_t)b * SS * EE + h*HD;
    const float* mrow = mask + ((size_t)(b*TT + t0 + srow)) * TT + scb;

    for (int st = 0; st < SS/128; st++) {
        const int sb = st * 128;
        const int s0b = sb & (TT - 1);

        __syncthreads();
#pragma unroll
        for (int i = tid; i < 2048; i += 256) {
            int r = i >> 4, c = (i & 15) * 4;
            size_t go = (size_t)(sb + r) * EE + c;
            *(uint2*)&sKh[r*LDK + c] = *(const uint2*)(kbh + go);
            *(uint2*)&sKl[r*LDK + c] = *(const uint2*)(kbl + go);
            *(uint2*)&sVh[r*LDK + c] = *(const uint2*)(vbh + go);
            *(uint2*)&sVl[r*LDK + c] = *(const uint2*)(vbl + go);
        }
        __syncthreads();

        // S = Q K^T (3-term split)
        {
            wmma::fragment<wmma::accumulator, 16, 16, 16, float> sacc[2][2];
#pragma unroll
            for (int i = 0; i < 2; i++)
#pragma unroll
                for (int j = 0; j < 2; j++) wmma::fill_fragment(sacc[i][j], 0.f);
#pragma unroll
            for (int k = 0; k < 4; k++) {
                wmma::fragment<wmma::matrix_a, 16,16,16, __nv_bfloat16, wmma::row_major> ah[2], al[2];
                wmma::fragment<wmma::matrix_b, 16,16,16, __nv_bfloat16, wmma::col_major> bh[2], bl[2];
#pragma unroll
                for (int i = 0; i < 2; i++) {
                    int rb = (wm*32 + i*16)*LDQ + k*16;
                    wmma::load_matrix_sync(ah[i], sQh + rb, LDQ);
                    wmma::load_matrix_sync(al[i], sQl + rb, LDQ);
                }
#pragma unroll
                for (int j = 0; j < 2; j++) {
                    int nb = (wn*32 + j*16)*LDK + k*16;
                    wmma::load_matrix_sync(bh[j], sKh + nb, LDK);
                    wmma::load_matrix_sync(bl[j], sKl + nb, LDK);
                }
#pragma unroll
                for (int i = 0; i < 2; i++)
#pragma unroll
                    for (int j = 0; j < 2; j++) {
                        wmma::mma_sync(sacc[i][j], ah[i], bh[j], sacc[i][j]);
                        wmma::mma_sync(sacc[i][j], ah[i], bl[j], sacc[i][j]);
                        wmma::mma_sync(sacc[i][j], al[i], bh[j], sacc[i][j]);
                    }
            }
#pragma unroll
            for (int i = 0; i < 2; i++)
#pragma unroll
                for (int j = 0; j < 2; j++)
                    wmma::store_matrix_sync(sS + (wm*32 + i*16)*LDSF + wn*32 + j*16,
                                            sacc[i][j], LDSF, wmma::mem_row_major);
        }
        __syncthreads();

        // softmax: p = exp(S + mask), row-sum; write split P
        float p[32];
        {
            const float* mr = mrow + s0b;
            float ls = 0.f;
#pragma unroll
            for (int jv = 0; jv < 8; jv++) {
                float4 mv = *(const float4*)(mr + jv*4);
                float s0 = sS[srow*LDSF + scb + jv*4 + 0] + mv.x;
                float s1 = sS[srow*LDSF + scb + jv*4 + 1] + mv.y;
                float s2 = sS[srow*LDSF + scb + jv*4 + 2] + mv.z;
                float s3 = sS[srow*LDSF + scb + jv*4 + 3] + mv.w;
                p[jv*4+0] = __expf(s0); p[jv*4+1] = __expf(s1);
                p[jv*4+2] = __expf(s2); p[jv*4+3] = __expf(s3);
                ls += p[jv*4+0] + p[jv*4+1] + p[jv*4+2] + p[jv*4+3];
            }
            ls += __shfl_xor_sync(0xffffffffu, ls, 1);
            ls += __shfl_xor_sync(0xffffffffu, ls, 2);
            __syncthreads();   // all S reads done before P overwrite
#pragma unroll
            for (int k2 = 0; k2 < 16; k2++) {
                float a0 = p[2*k2], a1 = p[2*k2+1];
                __nv_bfloat16 h0 = __float2bfloat16(a0);
                __nv_bfloat16 h1 = __float2bfloat16(a1);
                __nv_bfloat162 hi; hi.x = h0; hi.y = h1;
                __nv_bfloat162 lo;
                lo.x = __float2bfloat16(a0 - __bfloat162float(h0));
                lo.y = __float2bfloat16(a1 - __bfloat162float(h1));
                *(__nv_bfloat162*)&sPh[srow*LDSF + scb + 2*k2] = hi;
                *(__nv_bfloat162*)&sPl[srow*LDSF + scb + 2*k2] = lo;
            }
            if ((tid & 3) == 0) sL[srow] += ls;
        }
        __syncthreads();

        // O += P V  (3-term split)
#pragma unroll
        for (int k = 0; k < 8; k++) {
            wmma::fragment<wmma::matrix_b, 16,16,16, __nv_bfloat16, wmma::row_major> vfh, vfl;
            wmma::load_matrix_sync(vfh, sVh + (k*16)*LDK + wn*16, LDK);
            wmma::load_matrix_sync(vfl, sVl + (k*16)*LDK + wn*16, LDK);
#pragma unroll
            for (int i = 0; i < 2; i++) {
                wmma::fragment<wmma::matrix_a, 16,16,16, __nv_bfloat16, wmma::row_major> pfh, pfl;
                wmma::load_matrix_sync(pfh, sPh + (wm*32 + i*16)*LDSF + k*16, LDSF);
                wmma::load_matrix_sync(pfl, sPl + (wm*32 + i*16)*LDSF + k*16, LDSF);
                wmma::mma_sync(oacc[i], pfh, vfh, oacc[i]);
                wmma::mma_sync(oacc[i], pfh, vfl, oacc[i]);
                wmma::mma_sync(oacc[i], pfl, vfh, oacc[i]);
            }
        }
    }

    __syncthreads();
    wmma::store_matrix_sync(sO + (wm*32 + 0)*LDQ + wn*16, oacc[0], LDQ, wmma::mem_row_major);
    wmma::store_matrix_sync(sO + (wm*32 + 16)*LDQ + wn*16, oacc[1], LDQ, wmma::mem_row_major);
    __syncthreads();

    // write out: O[b, t0+r, h*HD + c] = sO / l
    {
        const int r = tid >> 2;
        const int cb = (tid & 3) * 16;
        const float inv = 1.f / sL[r];
        float* ob = O + ((size_t)(b*TT + t0 + r)) * EE + h*HD + cb;
#pragma unroll
        for (int v = 0; v < 4; v++) {
            float4 o = *(const float4*)&sO[r*LDQ + cb + v*4];
            o.x *= inv; o.y *= inv; o.z *= inv; o.w *= inv;
            *(float4*)(ob + v*4) = o;
        }
    }
}

// ---------------------------------------------------------------------------
extern "C" void kernel_launch(void* const* d_in, const int* in_sizes, int n_in,
                              void* d_out, int out_size) {
    const float* x    = (const float*)d_in[0];
    const float* mask = (const float*)d_in[1];
    const float* Wq   = (const float*)d_in[2];
    const float* bq   = (const float*)d_in[3];
    const float* Wk   = (const float*)d_in[4];
    const float* bk   = (const float*)d_in[5];
    const float* Wv   = (const float*)d_in[6];
    const float* bv   = (const float*)d_in[7];
    const float* Wo   = (const float*)d_in[8];
    const float* bo   = (const float*)d_in[9];
    float* out = (float*)d_out;

    __nv_bfloat16 *Qhp, *Qlp, *Khp, *Klp, *Vhp, *Vlp;
    float *AOp;
    cudaGetSymbolAddress((void**)&Qhp, g_Qh);
    cudaGetSymbolAddress((void**)&Qlp, g_Ql);
    cudaGetSymbolAddress((void**)&Khp, g_Kh);
    cudaGetSymbolAddress((void**)&Klp, g_Kl);
    cudaGetSymbolAddress((void**)&Vhp, g_Vh);
    cudaGetSymbolAddress((void**)&Vlp, g_Vl);
    cudaGetSymbolAddress((void**)&AOp, g_AO);

    static bool attr_done = false;
    if (!attr_done) {
        cudaFuncSetAttribute(sgemm_tc<0>, cudaFuncAttributeMaxDynamicSharedMemorySize, SG_SMEM);
        cudaFuncSetAttribute(sgemm_tc<1>, cudaFuncAttributeMaxDynamicSharedMemorySize, SG_SMEM);
        cudaFuncSetAttribute(flash_tc, cudaFuncAttributeMaxDynamicSharedMemorySize, FL_SMEM);
        attr_done = true;
    }

    dim3 blk(256);
    // Q (scaled) -> bf16 split
    sgemm_tc<1><<<dim3(EE/128, (BB*TT)/128), blk, SG_SMEM>>>(
        x, Wq, bq, nullptr, Qhp, Qlp, EE, EE, QSCALE);
    // K -> bf16 split
    sgemm_tc<1><<<dim3((MULT*EE)/128, (BB*TT)/128), blk, SG_SMEM>>>(
        x, Wk, bk, nullptr, Khp, Klp, MULT*EE, EE, 1.f);
    // V -> bf16 split
    sgemm_tc<1><<<dim3((MULT*EE)/128, (BB*TT)/128), blk, SG_SMEM>>>(
        x, Wv, bv, nullptr, Vhp, Vlp, MULT*EE, EE, 1.f);
    // flash attention -> g_AO fp32
    flash_tc<<<dim3(TT/64, HH, BB), blk, FL_SMEM>>>(
        Qhp, Qlp, Khp, Klp, Vhp, Vlp, mask, AOp);
    // out = AO Wo^T + bo (fp32 out)
    sgemm_tc<0><<<dim3(EE/128, (BB*TT)/128), blk, SG_SMEM>>>(
        AOp, Wo, bo, out, nullptr, nullptr, EE, EE, 1.f);
}

// round 6
// speedup vs baseline: 3.0516x; 1.0600x over previous
#include <cuda_runtime.h>
#include <cuda_bf16.h>
#include <mma.h>

using namespace nvcuda;

// Problem constants
#define BB 4
#define TT 1024
#define EE 1024
#define HH 16
#define HD 64
#define MULT 2
#define SS (TT*MULT)
static constexpr float QSCALE = 0.125f;  // HD^-0.5

// Scratch (allocation-free rule: __device__ globals)
__device__ __nv_bfloat16 g_xh[BB*TT*EE], g_xl[BB*TT*EE];
__device__ __nv_bfloat16 g_Wqh[EE*EE],      g_Wql[EE*EE];
__device__ __nv_bfloat16 g_Wkh[MULT*EE*EE], g_Wkl[MULT*EE*EE];
__device__ __nv_bfloat16 g_Wvh[MULT*EE*EE], g_Wvl[MULT*EE*EE];
__device__ __nv_bfloat16 g_Woh[EE*EE],      g_Wol[EE*EE];
__device__ __nv_bfloat16 g_Qh[BB*TT*EE],  g_Ql[BB*TT*EE];
__device__ __nv_bfloat16 g_Kh[BB*SS*EE],  g_Kl[BB*SS*EE];
__device__ __nv_bfloat16 g_Vh[BB*SS*EE],  g_Vl[BB*SS*EE];
__device__ __nv_bfloat16 g_AOh[BB*TT*EE], g_AOl[BB*TT*EE];

// ---------------------------------------------------------------------------
// Elementwise fp32 -> bf16 (hi, lo) split. n4 = n/4.
// ---------------------------------------------------------------------------
__global__ __launch_bounds__(256) void split_f32(
    const float* __restrict__ src, __nv_bfloat16* __restrict__ h,
    __nv_bfloat16* __restrict__ l, int n4)
{
    int i = blockIdx.x * blockDim.x + threadIdx.x;
    if (i >= n4) return;
    float4 v = ((const float4*)src)[i];
    __nv_bfloat16 h0 = __float2bfloat16(v.x);
    __nv_bfloat16 h1 = __float2bfloat16(v.y);
    __nv_bfloat16 h2 = __float2bfloat16(v.z);
    __nv_bfloat16 h3 = __float2bfloat16(v.w);
    __nv_bfloat162 hh0; hh0.x = h0; hh0.y = h1;
    __nv_bfloat162 hh1; hh1.x = h2; hh1.y = h3;
    __nv_bfloat162 ll0, ll1;
    ll0.x = __float2bfloat16(v.x - __bfloat162float(h0));
    ll0.y = __float2bfloat16(v.y - __bfloat162float(h1));
    ll1.x = __float2bfloat16(v.z - __bfloat162float(h2));
    ll1.y = __float2bfloat16(v.w - __bfloat162float(h3));
    ((__nv_bfloat162*)h)[i*2]   = hh0;
    ((__nv_bfloat162*)h)[i*2+1] = hh1;
    ((__nv_bfloat162*)l)[i*2]   = ll0;
    ((__nv_bfloat162*)l)[i*2+1] = ll1;
}

// ---------------------------------------------------------------------------
// Tensor-core GEMM on pre-split bf16 inputs (3-term, fp32 accum):
//   C[m,n] = (sum_k A[m,k]*W[n,k] + bias[n]) * scale
// OMODE 0: fp32 C. 1: bf16 split (Ch,Cl).
// Tile 128x128, k-chunk 32, double-buffered smem, 256 threads / 8 warps.
// ---------------------------------------------------------------------------
#define LDT 40
#define MAT (128*LDT)
#define SG_SMEM (2*4*MAT*2)

template<int OMODE>
__global__ __launch_bounds__(256) void sgemm_bs(
    const __nv_bfloat16* __restrict__ Ah, const __nv_bfloat16* __restrict__ Al,
    const __nv_bfloat16* __restrict__ Wh, const __nv_bfloat16* __restrict__ Wl,
    const float* __restrict__ bias, float* __restrict__ C,
    __nv_bfloat16* __restrict__ Ch, __nv_bfloat16* __restrict__ Cl,
    int N, int K, float scale)
{
    extern __shared__ __nv_bfloat16 sm_tc[];

    const int tid = threadIdx.x;
    const int m0 = blockIdx.y * 128;
    const int n0 = blockIdx.x * 128;
    const int wid = tid >> 5;
    const int wm = wid >> 2;
    const int wn = wid & 3;

    wmma::fragment<wmma::accumulator, 16, 16, 16, float> acc[4][2];
#pragma unroll
    for (int i = 0; i < 4; i++)
#pragma unroll
        for (int j = 0; j < 2; j++) wmma::fill_fragment(acc[i][j], 0.f);

    // load slots: slot = tid + t*256, t<2; r = slot>>2 (0..127), c8 = (slot&3)*8
    const __nv_bfloat16* gsrc[4];
    gsrc[0] = Ah + (size_t)m0 * K; gsrc[1] = Al + (size_t)m0 * K;
    gsrc[2] = Wh + (size_t)n0 * K; gsrc[3] = Wl + (size_t)n0 * K;

#define LOAD_CHUNK(dst4, kc) { \
    _Pragma("unroll") \
    for (int mtx = 0; mtx < 4; mtx++) { \
        _Pragma("unroll") \
        for (int t = 0; t < 2; t++) { \
            int slot = tid + t*256; \
            int r = slot >> 2, c8 = (slot & 3) * 8; \
            dst4[mtx][t] = *(const uint4*)(gsrc[mtx] + (size_t)r*K + (kc) + c8); \
        } } }

#define STORE_CHUNK(bufbase, src4) { \
    _Pragma("unroll") \
    for (int mtx = 0; mtx < 4; mtx++) { \
        __nv_bfloat16* sd = bufbase + mtx*MAT; \
        _Pragma("unroll") \
        for (int t = 0; t < 2; t++) { \
            int slot = tid + t*256; \
            int r = slot >> 2, c8 = (slot & 3) * 8; \
            *(uint4*)(sd + r*LDT + c8) = src4[mtx][t]; \
        } } }

    {
        uint4 v[4][2];
        LOAD_CHUNK(v, 0);
        STORE_CHUNK(sm_tc, v);
    }
    __syncthreads();

    const int NC = K >> 5;
    for (int c = 0; c < NC; c++) {
        const bool more = (c + 1 < NC);
        uint4 v[4][2];
        if (more) LOAD_CHUNK(v, (c + 1) * 32);

        {
            const __nv_bfloat16* buf = sm_tc + (size_t)(c & 1) * 4 * MAT;
            const __nv_bfloat16* sAh = buf;
            const __nv_bfloat16* sAl = buf + MAT;
            const __nv_bfloat16* sWh = buf + 2*MAT;
            const __nv_bfloat16* sWl = buf + 3*MAT;
#pragma unroll
            for (int kf = 0; kf < 2; kf++) {
                const int k0 = kf * 16;
                wmma::fragment<wmma::matrix_a, 16,16,16, __nv_bfloat16, wmma::row_major> ah[4], al[4];
                wmma::fragment<wmma::matrix_b, 16,16,16, __nv_bfloat16, wmma::col_major> bh[2], bl[2];
#pragma unroll
                for (int i = 0; i < 4; i++) {
                    int rbase = (wm*64 + i*16) * LDT + k0;
                    wmma::load_matrix_sync(ah[i], sAh + rbase, LDT);
                    wmma::load_matrix_sync(al[i], sAl + rbase, LDT);
                }
#pragma unroll
                for (int j = 0; j < 2; j++) {
                    int nbase = (wn*32 + j*16) * LDT + k0;
                    wmma::load_matrix_sync(bh[j], sWh + nbase, LDT);
                    wmma::load_matrix_sync(bl[j], sWl + nbase, LDT);
                }
#pragma unroll
                for (int i = 0; i < 4; i++)
#pragma unroll
                    for (int j = 0; j < 2; j++) {
                        wmma::mma_sync(acc[i][j], ah[i], bh[j], acc[i][j]);
                        wmma::mma_sync(acc[i][j], ah[i], bl[j], acc[i][j]);
                        wmma::mma_sync(acc[i][j], al[i], bh[j], acc[i][j]);
                    }
            }
        }
        if (more) {
            __nv_bfloat16* buf = sm_tc + (size_t)((c + 1) & 1) * 4 * MAT;
            STORE_CHUNK(buf, v);
        }
        __syncthreads();
    }

    // epilogue
    float* ep = (float*)sm_tc + wid * (16*20);
    const int lane = tid & 31;
#pragma unroll
    for (int i = 0; i < 4; i++) {
#pragma unroll
        for (int j = 0; j < 2; j++) {
            wmma::store_matrix_sync(ep, acc[i][j], 20, wmma::mem_row_major);
            __syncwarp();
#pragma unroll
            for (int e = 0; e < 8; e++) {
                int idx = lane * 8 + e;
                int r = idx >> 4, cc = idx & 15;
                int m = m0 + wm*64 + i*16 + r;
                int n = n0 + wn*32 + j*16 + cc;
                float v = (ep[r*20 + cc] + bias[n]) * scale;
                if (OMODE == 0) {
                    C[(size_t)m * N + n] = v;
                } else {
                    __nv_bfloat16 hh = __float2bfloat16(v);
                    Ch[(size_t)m * N + n] = hh;
                    Cl[(size_t)m * N + n] = __float2bfloat16(v - __bfloat162float(hh));
                }
            }
            __syncwarp();
        }
    }
}

// ---------------------------------------------------------------------------
// Tensor-core flash attention, 512 threads = 16 warps.
// 64 queries x 128 keys per tile. No-max-shift softmax (scores O(1)).
// QK: warp (wm 0..1, wn 0..7) -> 32x16 S block (2 frags).
// PV: warp (wm2 0..3, wn2 0..3) -> 16x16 O block (1 frag).
// Output written as split bf16 (AOh, AOl).
// ---------------------------------------------------------------------------
#define LDQ 72
#define LDK 72
#define LDSF 136
#define OFF_QH 0
#define OFF_QL 9216
#define OFF_KH 18432
#define OFF_KL 36864
#define OFF_VH 55296
#define OFF_VL 73728
#define OFF_S  92160
#define OFF_PH 92160
#define OFF_PL 109568
#define OFF_L  126976
#define FL_SMEM 127232

__global__ __launch_bounds__(512) void flash_tc(
    const __nv_bfloat16* __restrict__ Qh, const __nv_bfloat16* __restrict__ Ql,
    const __nv_bfloat16* __restrict__ Kh, const __nv_bfloat16* __restrict__ Kl,
    const __nv_bfloat16* __restrict__ Vh, const __nv_bfloat16* __restrict__ Vl,
    const float* __restrict__ mask,
    __nv_bfloat16* __restrict__ AOh, __nv_bfloat16* __restrict__ AOl)
{
    extern __shared__ char smraw[];
    __nv_bfloat16* sQh = (__nv_bfloat16*)(smraw + OFF_QH);  // 64x72
    __nv_bfloat16* sQl = (__nv_bfloat16*)(smraw + OFF_QL);
    __nv_bfloat16* sKh = (__nv_bfloat16*)(smraw + OFF_KH);  // 128x72
    __nv_bfloat16* sKl = (__nv_bfloat16*)(smraw + OFF_KL);
    __nv_bfloat16* sVh = (__nv_bfloat16*)(smraw + OFF_VH);  // 128x72
    __nv_bfloat16* sVl = (__nv_bfloat16*)(smraw + OFF_VL);
    float*         sS  = (float*)(smraw + OFF_S);           // 64x136 fp32
    __nv_bfloat16* sPh = (__nv_bfloat16*)(smraw + OFF_PH);  // alias
    __nv_bfloat16* sPl = (__nv_bfloat16*)(smraw + OFF_PL);  // alias
    float*         sO  = (float*)(smraw + OFF_S);           // alias 64x72 fp32
    float*         sL  = (float*)(smraw + OFF_L);

    const int tid = threadIdx.x;
    const int t0 = blockIdx.x * 64;
    const int h  = blockIdx.y;
    const int b  = blockIdx.z;
    const int wid = tid >> 5;
    const int wm = wid >> 3, wn = wid & 7;      // QK map
    const int wm2 = wid >> 2, wn2 = wid & 3;    // PV map
    const int srow = tid >> 3;                  // softmax row 0..63
    const int sc   = (tid & 7) * 16;            // softmax col base

    // Q tiles: 64x64, 512 uint4 slots, 1 per thread per matrix
    {
        const __nv_bfloat16* qh = Qh + ((size_t)(b*TT + t0)) * EE + h*HD;
        const __nv_bfloat16* ql = Ql + ((size_t)(b*TT + t0)) * EE + h*HD;
        int r = tid >> 3, c8 = (tid & 7) * 8;
        *(uint4*)&sQh[r*LDQ + c8] = *(const uint4*)(qh + (size_t)r*EE + c8);
        *(uint4*)&sQl[r*LDQ + c8] = *(const uint4*)(ql + (size_t)r*EE + c8);
        if (tid < 64) sL[tid] = 0.f;
    }

    wmma::fragment<wmma::accumulator, 16, 16, 16, float> oacc;
    wmma::fill_fragment(oacc, 0.f);

    const __nv_bfloat16* kbh = Kh + (size_t)b * SS * EE + h*HD;
    const __nv_bfloat16* kbl = Kl + (size_t)b * SS * EE + h*HD;
    const __nv_bfloat16* vbh = Vh + (size_t)b * SS * EE + h*HD;
    const __nv_bfloat16* vbl = Vl + (size_t)b * SS * EE + h*HD;
    const float* mrow = mask + ((size_t)(b*TT + t0 + srow)) * TT + sc;

    for (int st = 0; st < SS/128; st++) {
        const int sb = st * 128;
        const int s0b = sb & (TT - 1);

        __syncthreads();
        // K/V tiles: 128x64 per matrix, 1024 uint4 slots, 2 per thread
#pragma unroll
        for (int t = 0; t < 2; t++) {
            int slot = tid + t*512;
            int r = slot >> 3, c8 = (slot & 7) * 8;
            size_t go = (size_t)(sb + r) * EE + c8;
            *(uint4*)&sKh[r*LDK + c8] = *(const uint4*)(kbh + go);
            *(uint4*)&sKl[r*LDK + c8] = *(const uint4*)(kbl + go);
            *(uint4*)&sVh[r*LDK + c8] = *(const uint4*)(vbh + go);
            *(uint4*)&sVl[r*LDK + c8] = *(const uint4*)(vbl + go);
        }
        __syncthreads();

        // S = Q K^T (3-term split): warp block 32 rows x 16 cols
        {
            wmma::fragment<wmma::accumulator, 16, 16, 16, float> sacc[2];
            wmma::fill_fragment(sacc[0], 0.f);
            wmma::fill_fragment(sacc[1], 0.f);
#pragma unroll
            for (int k = 0; k < 4; k++) {
                wmma::fragment<wmma::matrix_a, 16,16,16, __nv_bfloat16, wmma::row_major> ah[2], al[2];
                wmma::fragment<wmma::matrix_b, 16,16,16, __nv_bfloat16, wmma::col_major> bh, bl;
#pragma unroll
                for (int i = 0; i < 2; i++) {
                    int rb = (wm*32 + i*16)*LDQ + k*16;
                    wmma::load_matrix_sync(ah[i], sQh + rb, LDQ);
                    wmma::load_matrix_sync(al[i], sQl + rb, LDQ);
                }
                {
                    int nb = (wn*16)*LDK + k*16;
                    wmma::load_matrix_sync(bh, sKh + nb, LDK);
                    wmma::load_matrix_sync(bl, sKl + nb, LDK);
                }
#pragma unroll
                for (int i = 0; i < 2; i++) {
                    wmma::mma_sync(sacc[i], ah[i], bh, sacc[i]);
                    wmma::mma_sync(sacc[i], ah[i], bl, sacc[i]);
                    wmma::mma_sync(sacc[i], al[i], bh, sacc[i]);
                }
            }
#pragma unroll
            for (int i = 0; i < 2; i++)
                wmma::store_matrix_sync(sS + (wm*32 + i*16)*LDSF + wn*16,
                                        sacc[i], LDSF, wmma::mem_row_major);
        }
        __syncthreads();

        // softmax: p = exp(S + mask); 8 threads per row, 16 cols each
        {
            float p[16];
            const float* mr = mrow + s0b;
            float ls = 0.f;
#pragma unroll
            for (int jv = 0; jv < 4; jv++) {
                float4 mv = *(const float4*)(mr + jv*4);
                float e0 = __expf(sS[srow*LDSF + sc + jv*4 + 0] + mv.x);
                float e1 = __expf(sS[srow*LDSF + sc + jv*4 + 1] + mv.y);
                float e2 = __expf(sS[srow*LDSF + sc + jv*4 + 2] + mv.z);
                float e3 = __expf(sS[srow*LDSF + sc + jv*4 + 3] + mv.w);
                p[jv*4+0] = e0; p[jv*4+1] = e1; p[jv*4+2] = e2; p[jv*4+3] = e3;
                ls += e0 + e1 + e2 + e3;
            }
            ls += __shfl_xor_sync(0xffffffffu, ls, 1);
            ls += __shfl_xor_sync(0xffffffffu, ls, 2);
            ls += __shfl_xor_sync(0xffffffffu, ls, 4);
            __syncthreads();   // all S reads done before P overwrite
#pragma unroll
            for (int k2 = 0; k2 < 8; k2++) {
                float a0 = p[2*k2], a1 = p[2*k2+1];
                __nv_bfloat16 h0 = __float2bfloat16(a0);
                __nv_bfloat16 h1 = __float2bfloat16(a1);
                __nv_bfloat162 hi; hi.x = h0; hi.y = h1;
                __nv_bfloat162 lo;
                lo.x = __float2bfloat16(a0 - __bfloat162float(h0));
                lo.y = __float2bfloat16(a1 - __bfloat162float(h1));
                *(__nv_bfloat162*)&sPh[srow*LDSF + sc + 2*k2] = hi;
                *(__nv_bfloat162*)&sPl[srow*LDSF + sc + 2*k2] = lo;
            }
            if ((tid & 7) == 0) sL[srow] += ls;
        }
        __syncthreads();

        // O += P V (3-term): warp block 16x16 of O
#pragma unroll
        for (int k = 0; k < 8; k++) {
            wmma::fragment<wmma::matrix_b, 16,16,16, __nv_bfloat16, wmma::row_major> vfh, vfl;
            wmma::load_matrix_sync(vfh, sVh + (k*16)*LDK + wn2*16, LDK);
            wmma::load_matrix_sync(vfl, sVl + (k*16)*LDK + wn2*16, LDK);
            wmma::fragment<wmma::matrix_a, 16,16,16, __nv_bfloat16, wmma::row_major> pfh, pfl;
            wmma::load_matrix_sync(pfh, sPh + (wm2*16)*LDSF + k*16, LDSF);
            wmma::load_matrix_sync(pfl, sPl + (wm2*16)*LDSF + k*16, LDSF);
            wmma::mma_sync(oacc, pfh, vfh, oacc);
            wmma::mma_sync(oacc, pfh, vfl, oacc);
            wmma::mma_sync(oacc, pfl, vfh, oacc);
        }
    }

    __syncthreads();
    wmma::store_matrix_sync(sO + (wm2*16)*LDQ + wn2*16, oacc, LDQ, wmma::mem_row_major);
    __syncthreads();

    // write out split bf16: AO[b, t0+r, h*HD + c] = sO / l
    {
        const int r = tid >> 3;
        const int c8 = (tid & 7) * 8;
        const float inv = 1.f / sL[r];
        size_t go = ((size_t)(b*TT + t0 + r)) * EE + h*HD + c8;
#pragma unroll
        for (int v = 0; v < 2; v++) {
            float4 o = *(const float4*)&sO[r*LDQ + c8 + v*4];
            float f[4] = {o.x*inv, o.y*inv, o.z*inv, o.w*inv};
#pragma unroll
            for (int e = 0; e < 2; e++) {
                float a0 = f[2*e], a1 = f[2*e+1];
                __nv_bfloat16 h0 = __float2bfloat16(a0);
                __nv_bfloat16 h1 = __float2bfloat16(a1);
                __nv_bfloat162 hi; hi.x = h0; hi.y = h1;
                __nv_bfloat162 lo;
                lo.x = __float2bfloat16(a0 - __bfloat162float(h0));
                lo.y = __float2bfloat16(a1 - __bfloat162float(h1));
                *(__nv_bfloat162*)(AOh + go + v*4 + e*2) = hi;
                *(__nv_bfloat162*)(AOl + go + v*4 + e*2) = lo;
            }
        }
    }
}

// ---------------------------------------------------------------------------
extern "C" void kernel_launch(void* const* d_in, const int* in_sizes, int n_in,
                              void* d_out, int out_size) {
    const float* x    = (const float*)d_in[0];
    const float* mask = (const float*)d_in[1];
    const float* Wq   = (const float*)d_in[2];
    const float* bq   = (const float*)d_in[3];
    const float* Wk   = (const float*)d_in[4];
    const float* bk   = (const float*)d_in[5];
    const float* Wv   = (const float*)d_in[6];
    const float* bv   = (const float*)d_in[7];
    const float* Wo   = (const float*)d_in[8];
    const float* bo   = (const float*)d_in[9];
    float* out = (float*)d_out;

    __nv_bfloat16 *xh, *xl, *Wqh, *Wql, *Wkh, *Wkl, *Wvh, *Wvl, *Woh, *Wol;
    __nv_bfloat16 *Qhp, *Qlp, *Khp, *Klp, *Vhp, *Vlp, *AOhp, *AOlp;
    cudaGetSymbolAddress((void**)&xh, g_xh);   cudaGetSymbolAddress((void**)&xl, g_xl);
    cudaGetSymbolAddress((void**)&Wqh, g_Wqh); cudaGetSymbolAddress((void**)&Wql, g_Wql);
    cudaGetSymbolAddress((void**)&Wkh, g_Wkh); cudaGetSymbolAddress((void**)&Wkl, g_Wkl);
    cudaGetSymbolAddress((void**)&Wvh, g_Wvh); cudaGetSymbolAddress((void**)&Wvl, g_Wvl);
    cudaGetSymbolAddress((void**)&Woh, g_Woh); cudaGetSymbolAddress((void**)&Wol, g_Wol);
    cudaGetSymbolAddress((void**)&Qhp, g_Qh);  cudaGetSymbolAddress((void**)&Qlp, g_Ql);
    cudaGetSymbolAddress((void**)&Khp, g_Kh);  cudaGetSymbolAddress((void**)&Klp, g_Kl);
    cudaGetSymbolAddress((void**)&Vhp, g_Vh);  cudaGetSymbolAddress((void**)&Vlp, g_Vl);
    cudaGetSymbolAddress((void**)&AOhp, g_AOh); cudaGetSymbolAddress((void**)&AOlp, g_AOl);

    static bool attr_done = false;
    if (!attr_done) {
        cudaFuncSetAttribute(sgemm_bs<0>, cudaFuncAttributeMaxDynamicSharedMemorySize, SG_SMEM);
        cudaFuncSetAttribute(sgemm_bs<1>, cudaFuncAttributeMaxDynamicSharedMemorySize, SG_SMEM);
        cudaFuncSetAttribute(flash_tc, cudaFuncAttributeMaxDynamicSharedMemorySize, FL_SMEM);
        attr_done = true;
    }

    // 1) pre-split inputs to bf16 hi/lo
    {
        int nx = BB*TT*EE/4;
        split_f32<<<(nx+255)/256, 256>>>(x, xh, xl, nx);
        int nw1 = EE*EE/4;
        split_f32<<<(nw1+255)/256, 256>>>(Wq, Wqh, Wql, nw1);
        split_f32<<<(nw1+255)/256, 256>>>(Wo, Woh, Wol, nw1);
        int nw2 = MULT*EE*EE/4;
        split_f32<<<(nw2+255)/256, 256>>>(Wk, Wkh, Wkl, nw2);
        split_f32<<<(nw2+255)/256, 256>>>(Wv, Wvh, Wvl, nw2);
    }

    dim3 blk(256);
    // 2) projections (bf16-split GEMMs)
    sgemm_bs<1><<<dim3(EE/128, (BB*TT)/128), blk, SG_SMEM>>>(
        xh, xl, Wqh, Wql, bq, nullptr, Qhp, Qlp, EE, EE, QSCALE);
    sgemm_bs<1><<<dim3((MULT*EE)/128, (BB*TT)/128), blk, SG_SMEM>>>(
        xh, xl, Wkh, Wkl, bk, nullptr, Khp, Klp, MULT*EE, EE, 1.f);
    sgemm_bs<1><<<dim3((MULT*EE)/128, (BB*TT)/128), blk, SG_SMEM>>>(
        xh, xl, Wvh, Wvl, bv, nullptr, Vhp, Vlp, MULT*EE, EE, 1.f);
    // 3) flash attention -> split bf16 AO
    flash_tc<<<dim3(TT/64, HH, BB), dim3(512), FL_SMEM>>>(
        Qhp, Qlp, Khp, Klp, Vhp, Vlp, mask, AOhp, AOlp);
    // 4) output projection (fp32 out)
    sgemm_bs<0><<<dim3(EE/128, (BB*TT)/128), blk, SG_SMEM>>>(
        AOhp, AOlp, Woh, Wol, bo, out, nullptr, nullptr, EE, EE, 1.f);
}

// round 8
// speedup vs baseline: 4.0936x; 1.3414x over previous
#include <cuda_runtime.h>
#include <cuda_bf16.h>
#include <cuda_fp16.h>
#include <mma.h>
#include <cstdint>

using namespace nvcuda;

// Problem constants
#define BB 4
#define TT 1024
#define EE 1024
#define HH 16
#define HD 64
#define MULT 2
#define SS (TT*MULT)
static constexpr float QSCALE = 0.125f;  // HD^-0.5

// Scratch (allocation-free rule: __device__ globals)
__device__ __nv_bfloat16 g_xh[BB*TT*EE], g_xl[BB*TT*EE];
__device__ __nv_bfloat16 g_Wqh[EE*EE],      g_Wql[EE*EE];
__device__ __nv_bfloat16 g_Wkh[MULT*EE*EE], g_Wkl[MULT*EE*EE];
__device__ __nv_bfloat16 g_Wvh[MULT*EE*EE], g_Wvl[MULT*EE*EE];
__device__ __nv_bfloat16 g_Woh[EE*EE],      g_Wol[EE*EE];
__device__ __half g_Qf[BB*TT*EE];          // fp16 single (scaled q)
__device__ __half g_Kf[BB*SS*EE];
__device__ __half g_Vf[BB*SS*EE];
__device__ __nv_bfloat16 g_AOh[BB*TT*EE], g_AOl[BB*TT*EE];

// ---------------------------------------------------------------------------
// Elementwise fp32 -> bf16 (hi, lo) split. n4 = n/4.
// ---------------------------------------------------------------------------
__global__ __launch_bounds__(256) void split_f32(
    const float* __restrict__ src, __nv_bfloat16* __restrict__ h,
    __nv_bfloat16* __restrict__ l, int n4)
{
    int i = blockIdx.x * blockDim.x + threadIdx.x;
    if (i >= n4) return;
    float4 v = ((const float4*)src)[i];
    __nv_bfloat16 h0 = __float2bfloat16(v.x);
    __nv_bfloat16 h1 = __float2bfloat16(v.y);
    __nv_bfloat16 h2 = __float2bfloat16(v.z);
    __nv_bfloat16 h3 = __float2bfloat16(v.w);
    __nv_bfloat162 hh0; hh0.x = h0; hh0.y = h1;
    __nv_bfloat162 hh1; hh1.x = h2; hh1.y = h3;
    __nv_bfloat162 ll0, ll1;
    ll0.x = __float2bfloat16(v.x - __bfloat162float(h0));
    ll0.y = __float2bfloat16(v.y - __bfloat162float(h1));
    ll1.x = __float2bfloat16(v.z - __bfloat162float(h2));
    ll1.y = __float2bfloat16(v.w - __bfloat162float(h3));
    ((__nv_bfloat162*)h)[i*2]   = hh0;
    ((__nv_bfloat162*)h)[i*2+1] = hh1;
    ((__nv_bfloat162*)l)[i*2]   = ll0;
    ((__nv_bfloat162*)l)[i*2+1] = ll1;
}

// ---------------------------------------------------------------------------
// Tensor-core GEMM on pre-split bf16 inputs (3-term, fp32 accum):
//   C[m,n] = (sum_k A[m,k]*W[n,k] + bias[n]) * scale
// OMODE 0: fp32 C. 1: bf16 split (Ch,Cl). 2: fp16 single (Cf).
// Tile 128x128, k-chunk 32, double-buffered smem, 256 threads / 8 warps.
// ---------------------------------------------------------------------------
#define LDT 40
#define MAT (128*LDT)
#define SG_SMEM (2*4*MAT*2)

template<int OMODE>
__global__ __launch_bounds__(256) void sgemm_bs(
    const __nv_bfloat16* __restrict__ Ah, const __nv_bfloat16* __restrict__ Al,
    const __nv_bfloat16* __restrict__ Wh, const __nv_bfloat16* __restrict__ Wl,
    const float* __restrict__ bias, float* __restrict__ C,
    __nv_bfloat16* __restrict__ Ch, __nv_bfloat16* __restrict__ Cl,
    __half* __restrict__ Cf,
    int N, int K, float scale)
{
    extern __shared__ __nv_bfloat16 sm_tc[];

    const int tid = threadIdx.x;
    const int m0 = blockIdx.y * 128;
    const int n0 = blockIdx.x * 128;
    const int wid = tid >> 5;
    const int wm = wid >> 2;
    const int wn = wid & 3;

    wmma::fragment<wmma::accumulator, 16, 16, 16, float> acc[4][2];
#pragma unroll
    for (int i = 0; i < 4; i++)
#pragma unroll
        for (int j = 0; j < 2; j++) wmma::fill_fragment(acc[i][j], 0.f);

    const __nv_bfloat16* gsrc[4];
    gsrc[0] = Ah + (size_t)m0 * K; gsrc[1] = Al + (size_t)m0 * K;
    gsrc[2] = Wh + (size_t)n0 * K; gsrc[3] = Wl + (size_t)n0 * K;

#define LOAD_CHUNK(dst4, kc) { \
    _Pragma("unroll") \
    for (int mtx = 0; mtx < 4; mtx++) { \
        _Pragma("unroll") \
        for (int t = 0; t < 2; t++) { \
            int slot = tid + t*256; \
            int r = slot >> 2, c8 = (slot & 3) * 8; \
            dst4[mtx][t] = *(const uint4*)(gsrc[mtx] + (size_t)r*K + (kc) + c8); \
        } } }

#define STORE_CHUNK(bufbase, src4) { \
    _Pragma("unroll") \
    for (int mtx = 0; mtx < 4; mtx++) { \
        __nv_bfloat16* sd = bufbase + mtx*MAT; \
        _Pragma("unroll") \
        for (int t = 0; t < 2; t++) { \
            int slot = tid + t*256; \
            int r = slot >> 2, c8 = (slot & 3) * 8; \
            *(uint4*)(sd + r*LDT + c8) = src4[mtx][t]; \
        } } }

    {
        uint4 v[4][2];
        LOAD_CHUNK(v, 0);
        STORE_CHUNK(sm_tc, v);
    }
    __syncthreads();

    const int NC = K >> 5;
    for (int c = 0; c < NC; c++) {
        const bool more = (c + 1 < NC);
        uint4 v[4][2];
        if (more) LOAD_CHUNK(v, (c + 1) * 32);

        {
            const __nv_bfloat16* buf = sm_tc + (size_t)(c & 1) * 4 * MAT;
            const __nv_bfloat16* sAh = buf;
            const __nv_bfloat16* sAl = buf + MAT;
            const __nv_bfloat16* sWh = buf + 2*MAT;
            const __nv_bfloat16* sWl = buf + 3*MAT;
#pragma unroll
            for (int kf = 0; kf < 2; kf++) {
                const int k0 = kf * 16;
                wmma::fragment<wmma::matrix_a, 16,16,16, __nv_bfloat16, wmma::row_major> ah[4], al[4];
                wmma::fragment<wmma::matrix_b, 16,16,16, __nv_bfloat16, wmma::col_major> bh[2], bl[2];
#pragma unroll
                for (int i = 0; i < 4; i++) {
                    int rbase = (wm*64 + i*16) * LDT + k0;
                    wmma::load_matrix_sync(ah[i], sAh + rbase, LDT);
                    wmma::load_matrix_sync(al[i], sAl + rbase, LDT);
                }
#pragma unroll
                for (int j = 0; j < 2; j++) {
                    int nbase = (wn*32 + j*16) * LDT + k0;
                    wmma::load_matrix_sync(bh[j], sWh + nbase, LDT);
                    wmma::load_matrix_sync(bl[j], sWl + nbase, LDT);
                }
#pragma unroll
                for (int i = 0; i < 4; i++)
#pragma unroll
                    for (int j = 0; j < 2; j++) {
                        wmma::mma_sync(acc[i][j], ah[i], bh[j], acc[i][j]);
                        wmma::mma_sync(acc[i][j], ah[i], bl[j], acc[i][j]);
                        wmma::mma_sync(acc[i][j], al[i], bh[j], acc[i][j]);
                    }
            }
        }
        if (more) {
            __nv_bfloat16* buf = sm_tc + (size_t)((c + 1) & 1) * 4 * MAT;
            STORE_CHUNK(buf, v);
        }
        __syncthreads();
    }

    // epilogue
    float* ep = (float*)sm_tc + wid * (16*20);
    const int lane = tid & 31;
#pragma unroll
    for (int i = 0; i < 4; i++) {
#pragma unroll
        for (int j = 0; j < 2; j++) {
            wmma::store_matrix_sync(ep, acc[i][j], 20, wmma::mem_row_major);
            __syncwarp();
#pragma unroll
            for (int e = 0; e < 8; e++) {
                int idx = lane * 8 + e;
                int r = idx >> 4, cc = idx & 15;
                int m = m0 + wm*64 + i*16 + r;
                int n = n0 + wn*32 + j*16 + cc;
                float v = (ep[r*20 + cc] + bias[n]) * scale;
                if (OMODE == 0) {
                    C[(size_t)m * N + n] = v;
                } else if (OMODE == 1) {
                    __nv_bfloat16 hh = __float2bfloat16(v);
                    Ch[(size_t)m * N + n] = hh;
                    Cl[(size_t)m * N + n] = __float2bfloat16(v - __bfloat162float(hh));
                } else {
                    Cf[(size_t)m * N + n] = __float2half_rn(v);
                }
            }
            __syncwarp();
        }
    }
}

// ---------------------------------------------------------------------------
// Flash attention, fp16 single-term, 512 threads = 16 warps.
// 64 queries x 128 keys per tile. No-max-shift softmax (scores O(1)).
// QK: warp (wm 0..1, wn 0..7) -> 32x16 S block.
// PV: warp (wm2 0..3, wn2 0..3) -> 16x16 O block.
// Output written as split bf16 (AOh, AOl) for the 3-term output projection.
// ---------------------------------------------------------------------------
#define LDQ 72
#define LDK 72
#define LDSF 136
#define OFF_Q  0                 // half 64x72   = 9216
#define OFF_K  9216              // half 128x72  = 18432
#define OFF_V  27648             // half 128x72  = 18432
#define OFF_S  46080             // float 64x136 = 34816 (aliased by P and O)
#define OFF_L  80896             // 64 floats
#define FL_SMEM 81152

__global__ __launch_bounds__(512) void flash_f16(
    const __half* __restrict__ Qf, const __half* __restrict__ Kf,
    const __half* __restrict__ Vf, const float* __restrict__ mask,
    __nv_bfloat16* __restrict__ AOh, __nv_bfloat16* __restrict__ AOl)
{
    extern __shared__ char smraw[];
    __half* sQ = (__half*)(smraw + OFF_Q);
    __half* sK = (__half*)(smraw + OFF_K);
    __half* sV = (__half*)(smraw + OFF_V);
    float*  sS = (float*)(smraw + OFF_S);
    __half* sP = (__half*)(smraw + OFF_S);    // alias (half 64x136 = 17408)
    float*  sO = (float*)(smraw + OFF_S);     // alias (float 64x72 = 18432)
    float*  sL = (float*)(smraw + OFF_L);

    const int tid = threadIdx.x;
    const int t0 = blockIdx.x * 64;
    const int h  = blockIdx.y;
    const int b  = blockIdx.z;
    const int wid = tid >> 5;
    const int wm = wid >> 3, wn = wid & 7;      // QK map
    const int wm2 = wid >> 2, wn2 = wid & 3;    // PV map
    const int srow = tid >> 3;                  // softmax row 0..63
    const int sc   = (tid & 7) * 16;            // softmax col base

    // Q tile: 64x64 halves = 512 uint4 slots (8 halves each)
    {
        const __half* q = Qf + ((size_t)(b*TT + t0)) * EE + h*HD;
        int r = tid >> 3, c8 = (tid & 7) * 8;
        *(uint4*)&sQ[r*LDQ + c8] = *(const uint4*)(q + (size_t)r*EE + c8);
        if (tid < 64) sL[tid] = 0.f;
    }

    wmma::fragment<wmma::accumulator, 16, 16, 16, float> oacc;
    wmma::fill_fragment(oacc, 0.f);

    const __half* kb = Kf + (size_t)b * SS * EE + h*HD;
    const __half* vb = Vf + (size_t)b * SS * EE + h*HD;
    const float* mrow = mask + ((size_t)(b*TT + t0 + srow)) * TT + sc;

    for (int st = 0; st < SS/128; st++) {
        const int sb = st * 128;
        const int s0b = sb & (TT - 1);

        __syncthreads();
        // K/V tiles: 128x64 halves each = 1024 uint4 slots, 2 per thread
#pragma unroll
        for (int t = 0; t < 2; t++) {
            int slot = tid + t*512;
            int r = slot >> 3, c8 = (slot & 7) * 8;
            size_t go = (size_t)(sb + r) * EE + c8;
            *(uint4*)&sK[r*LDK + c8] = *(const uint4*)(kb + go);
            *(uint4*)&sV[r*LDK + c8] = *(const uint4*)(vb + go);
        }
        __syncthreads();

        // S = Q K^T: warp block 32 rows x 16 cols
        {
            wmma::fragment<wmma::accumulator, 16, 16, 16, float> sacc[2];
            wmma::fill_fragment(sacc[0], 0.f);
            wmma::fill_fragment(sacc[1], 0.f);
#pragma unroll
            for (int k = 0; k < 4; k++) {
                wmma::fragment<wmma::matrix_a, 16,16,16, __half, wmma::row_major> af[2];
                wmma::fragment<wmma::matrix_b, 16,16,16, __half, wmma::col_major> bf;
#pragma unroll
                for (int i = 0; i < 2; i++)
                    wmma::load_matrix_sync(af[i], sQ + (wm*32 + i*16)*LDQ + k*16, LDQ);
                wmma::load_matrix_sync(bf, sK + (wn*16)*LDK + k*16, LDK);
#pragma unroll
                for (int i = 0; i < 2; i++)
                    wmma::mma_sync(sacc[i], af[i], bf, sacc[i]);
            }
#pragma unroll
            for (int i = 0; i < 2; i++)
                wmma::store_matrix_sync(sS + (wm*32 + i*16)*LDSF + wn*16,
                                        sacc[i], LDSF, wmma::mem_row_major);
        }
        __syncthreads();

        // softmax: p = exp(S + mask); 8 threads per row, 16 cols each
        {
            float p[16];
            const float* mr = mrow + s0b;
            float ls = 0.f;
#pragma unroll
            for (int jv = 0; jv < 4; jv++) {
                float4 mv = *(const float4*)(mr + jv*4);
                float e0 = __expf(sS[srow*LDSF + sc + jv*4 + 0] + mv.x);
                float e1 = __expf(sS[srow*LDSF + sc + jv*4 + 1] + mv.y);
                float e2 = __expf(sS[srow*LDSF + sc + jv*4 + 2] + mv.z);
                float e3 = __expf(sS[srow*LDSF + sc + jv*4 + 3] + mv.w);
                p[jv*4+0] = e0; p[jv*4+1] = e1; p[jv*4+2] = e2; p[jv*4+3] = e3;
                ls += e0 + e1 + e2 + e3;
            }
            ls += __shfl_xor_sync(0xffffffffu, ls, 1);
            ls += __shfl_xor_sync(0xffffffffu, ls, 2);
            ls += __shfl_xor_sync(0xffffffffu, ls, 4);
            __syncthreads();   // all S reads done before P overwrite
#pragma unroll
            for (int k2 = 0; k2 < 8; k2++) {
                __half2 pr = __floats2half2_rn(p[2*k2], p[2*k2+1]);
                *(__half2*)&sP[srow*LDSF + sc + 2*k2] = pr;
            }
            if ((tid & 7) == 0) sL[srow] += ls;
        }
        __syncthreads();

        // O += P V: warp block 16x16 of O
#pragma unroll
        for (int k = 0; k < 8; k++) {
            wmma::fragment<wmma::matrix_b, 16,16,16, __half, wmma::row_major> vf;
            wmma::load_matrix_sync(vf, sV + (k*16)*LDK + wn2*16, LDK);
            wmma::fragment<wmma::matrix_a, 16,16,16, __half, wmma::row_major> pf;
            wmma::load_matrix_sync(pf, sP + (wm2*16)*LDSF + k*16, LDSF);
            wmma::mma_sync(oacc, pf, vf, oacc);
        }
    }

    __syncthreads();
    wmma::store_matrix_sync(sO + (wm2*16)*LDQ + wn2*16, oacc, LDQ, wmma::mem_row_major);
    __syncthreads();

    // write out split bf16: AO[b, t0+r, h*HD + c] = sO / l
    {
        const int r = tid >> 3;
        const int c8 = (tid & 7) * 8;
        const float inv = 1.f / sL[r];
        size_t go = ((size_t)(b*TT + t0 + r)) * EE + h*HD + c8;
#pragma unroll
        for (int v = 0; v < 2; v++) {
            float4 o = *(const float4*)&sO[r*LDQ + c8 + v*4];
            float f[4] = {o.x*inv, o.y*inv, o.z*inv, o.w*inv};
#pragma unroll
            for (int e = 0; e < 2; e++) {
                float a0 = f[2*e], a1 = f[2*e+1];
                __nv_bfloat16 h0 = __float2bfloat16(a0);
                __nv_bfloat16 h1 = __float2bfloat16(a1);
                __nv_bfloat162 hi; hi.x = h0; hi.y = h1;
                __nv_bfloat162 lo;
                lo.x = __float2bfloat16(a0 - __bfloat162float(h0));
                lo.y = __float2bfloat16(a1 - __bfloat162float(h1));
                *(__nv_bfloat162*)(AOh + go + v*4 + e*2) = hi;
                *(__nv_bfloat162*)(AOl + go + v*4 + e*2) = lo;
            }
        }
    }
}

// ---------------------------------------------------------------------------
extern "C" void kernel_launch(void* const* d_in, const int* in_sizes, int n_in,
                              void* d_out, int out_size) {
    const float* x    = (const float*)d_in[0];
    const float* mask = (const float*)d_in[1];
    const float* Wq   = (const float*)d_in[2];
    const float* bq   = (const float*)d_in[3];
    const float* Wk   = (const float*)d_in[4];
    const float* bk   = (const float*)d_in[5];
    const float* Wv   = (const float*)d_in[6];
    const float* bv   = (const float*)d_in[7];
    const float* Wo   = (const float*)d_in[8];
    const float* bo   = (const float*)d_in[9];
    float* out = (float*)d_out;

    __nv_bfloat16 *xh, *xl, *Wqh, *Wql, *Wkh, *Wkl, *Wvh, *Wvl, *Woh, *Wol;
    __nv_bfloat16 *AOhp, *AOlp;
    __half *Qfp, *Kfp, *Vfp;
    cudaGetSymbolAddress((void**)&xh, g_xh);   cudaGetSymbolAddress((void**)&xl, g_xl);
    cudaGetSymbolAddress((void**)&Wqh, g_Wqh); cudaGetSymbolAddress((void**)&Wql, g_Wql);
    cudaGetSymbolAddress((void**)&Wkh, g_Wkh); cudaGetSymbolAddress((void**)&Wkl, g_Wkl);
    cudaGetSymbolAddress((void**)&Wvh, g_Wvh); cudaGetSymbolAddress((void**)&Wvl, g_Wvl);
    cudaGetSymbolAddress((void**)&Woh, g_Woh); cudaGetSymbolAddress((void**)&Wol, g_Wol);
    cudaGetSymbolAddress((void**)&Qfp, g_Qf);
    cudaGetSymbolAddress((void**)&Kfp, g_Kf);
    cudaGetSymbolAddress((void**)&Vfp, g_Vf);
    cudaGetSymbolAddress((void**)&AOhp, g_AOh); cudaGetSymbolAddress((void**)&AOlp, g_AOl);

    static bool attr_done = false;
    if (!attr_done) {
        cudaFuncSetAttribute(sgemm_bs<0>, cudaFuncAttributeMaxDynamicSharedMemorySize, SG_SMEM);
        cudaFuncSetAttribute(sgemm_bs<1>, cudaFuncAttributeMaxDynamicSharedMemorySize, SG_SMEM);
        cudaFuncSetAttribute(sgemm_bs<2>, cudaFuncAttributeMaxDynamicSharedMemorySize, SG_SMEM);
        cudaFuncSetAttribute(flash_f16, cudaFuncAttributeMaxDynamicSharedMemorySize, FL_SMEM);
        attr_done = true;
    }

    // 1) pre-split inputs to bf16 hi/lo
    {
        int nx = BB*TT*EE/4;
        split_f32<<<(nx+255)/256, 256>>>(x, xh, xl, nx);
        int nw1 = EE*EE/4;
        split_f32<<<(nw1+255)/256, 256>>>(Wq, Wqh, Wql, nw1);
        split_f32<<<(nw1+255)/256, 256>>>(Wo, Woh, Wol, nw1);
        int nw2 = MULT*EE*EE/4;
        split_f32<<<(nw2+255)/256, 256>>>(Wk, Wkh, Wkl, nw2);
        split_f32<<<(nw2+255)/256, 256>>>(Wv, Wvh, Wvl, nw2);
    }

    dim3 blk(256);
    // 2) projections (bf16-split GEMMs, fp16-single outputs for flash)
    sgemm_bs<2><<<dim3(EE/128, (BB*TT)/128), blk, SG_SMEM>>>(
        xh, xl, Wqh, Wql, bq, nullptr, nullptr, nullptr, Qfp, EE, EE, QSCALE);
    sgemm_bs<2><<<dim3((MULT*EE)/128, (BB*TT)/128), blk, SG_SMEM>>>(
        xh, xl, Wkh, Wkl, bk, nullptr, nullptr, nullptr, Kfp, MULT*EE, EE, 1.f);
    sgemm_bs<2><<<dim3((MULT*EE)/128, (BB*TT)/128), blk, SG_SMEM>>>(
        xh, xl, Wvh, Wvl, bv, nullptr, nullptr, nullptr, Vfp, MULT*EE, EE, 1.f);
    // 3) flash attention (fp16 single) -> split bf16 AO
    flash_f16<<<dim3(TT/64, HH, BB), dim3(512), FL_SMEM>>>(
        Qfp, Kfp, Vfp, mask, AOhp, AOlp);
    // 4) output projection (bf16 3-term, fp32 out)
    sgemm_bs<0><<<dim3(EE/128, (BB*TT)/128), blk, SG_SMEM>>>(
        AOhp, AOlp, Woh, Wol, bo, out, nullptr, nullptr, nullptr, EE, EE, 1.f);
}

// round 9
// speedup vs baseline: 4.1615x; 1.0166x over previous
#include <cuda_runtime.h>
#include <cuda_bf16.h>
#include <cuda_fp16.h>
#include <mma.h>
#include <cstdint>

using namespace nvcuda;

// Problem constants
#define BB 4
#define TT 1024
#define EE 1024
#define HH 16
#define HD 64
#define MULT 2
#define SS (TT*MULT)
static constexpr float QSCALE = 0.125f;  // HD^-0.5

// Scratch (allocation-free rule: __device__ globals)
__device__ __nv_bfloat16 g_xh[BB*TT*EE], g_xl[BB*TT*EE];
__device__ __nv_bfloat16 g_Wqh[EE*EE],      g_Wql[EE*EE];
__device__ __nv_bfloat16 g_Wkh[MULT*EE*EE], g_Wkl[MULT*EE*EE];
__device__ __nv_bfloat16 g_Wvh[MULT*EE*EE], g_Wvl[MULT*EE*EE];
__device__ __nv_bfloat16 g_Woh[EE*EE],      g_Wol[EE*EE];
__device__ __half g_Qf[BB*TT*EE];          // fp16 single (scaled q)
__device__ __half g_Kf[BB*SS*EE];
__device__ __half g_Vf[BB*SS*EE];
__device__ __nv_bfloat16 g_AOh[BB*TT*EE], g_AOl[BB*TT*EE];

// ---------------------------------------------------------------------------
// Elementwise fp32 -> bf16 (hi, lo) split. n4 = n/4.
// ---------------------------------------------------------------------------
__global__ __launch_bounds__(256) void split_f32(
    const float* __restrict__ src, __nv_bfloat16* __restrict__ h,
    __nv_bfloat16* __restrict__ l, int n4)
{
    int i = blockIdx.x * blockDim.x + threadIdx.x;
    if (i >= n4) return;
    float4 v = ((const float4*)src)[i];
    __nv_bfloat16 h0 = __float2bfloat16(v.x);
    __nv_bfloat16 h1 = __float2bfloat16(v.y);
    __nv_bfloat16 h2 = __float2bfloat16(v.z);
    __nv_bfloat16 h3 = __float2bfloat16(v.w);
    __nv_bfloat162 hh0; hh0.x = h0; hh0.y = h1;
    __nv_bfloat162 hh1; hh1.x = h2; hh1.y = h3;
    __nv_bfloat162 ll0, ll1;
    ll0.x = __float2bfloat16(v.x - __bfloat162float(h0));
    ll0.y = __float2bfloat16(v.y - __bfloat162float(h1));
    ll1.x = __float2bfloat16(v.z - __bfloat162float(h2));
    ll1.y = __float2bfloat16(v.w - __bfloat162float(h3));
    ((__nv_bfloat162*)h)[i*2]   = hh0;
    ((__nv_bfloat162*)h)[i*2+1] = hh1;
    ((__nv_bfloat162*)l)[i*2]   = ll0;
    ((__nv_bfloat162*)l)[i*2+1] = ll1;
}

// ---------------------------------------------------------------------------
// Tensor-core GEMM on pre-split bf16 inputs (3-term, fp32 accum):
//   C[m,n] = (sum_k A[m,k]*W[n,k] + bias[n]) * scale
// OMODE 0: fp32 C. 2: fp16 single (Cf).
// Tile 128x128, k-chunk 32, double-buffered smem.
// 512 threads = 16 warps in 4x4 grid; warp owns 32x32 (2x2 frags).
// ---------------------------------------------------------------------------
#define LDT 40
#define MAT (128*LDT)
#define SG_SMEM (2*4*MAT*2)

template<int OMODE>
__global__ __launch_bounds__(512) void sgemm_bs(
    const __nv_bfloat16* __restrict__ Ah, const __nv_bfloat16* __restrict__ Al,
    const __nv_bfloat16* __restrict__ Wh, const __nv_bfloat16* __restrict__ Wl,
    const float* __restrict__ bias, float* __restrict__ C,
    __half* __restrict__ Cf,
    int N, int K, float scale)
{
    extern __shared__ __nv_bfloat16 sm_tc[];

    const int tid = threadIdx.x;
    const int m0 = blockIdx.y * 128;
    const int n0 = blockIdx.x * 128;
    const int wid = tid >> 5;
    const int wm = wid >> 2;        // 0..3 (32-row band)
    const int wn = wid & 3;         // 0..3 (32-col band)

    wmma::fragment<wmma::accumulator, 16, 16, 16, float> acc[2][2];
#pragma unroll
    for (int i = 0; i < 2; i++)
#pragma unroll
        for (int j = 0; j < 2; j++) wmma::fill_fragment(acc[i][j], 0.f);

    const __nv_bfloat16* gsrc[4];
    gsrc[0] = Ah + (size_t)m0 * K; gsrc[1] = Al + (size_t)m0 * K;
    gsrc[2] = Wh + (size_t)n0 * K; gsrc[3] = Wl + (size_t)n0 * K;

    // 512 threads: per chunk each mat is 128x32 halves = 512 uint4 slots
    const int lr  = tid >> 2;            // row 0..127
    const int lc8 = (tid & 3) * 8;       // col 0/8/16/24

#define LOAD_CHUNK(dst4, kc) { \
    _Pragma("unroll") \
    for (int mtx = 0; mtx < 4; mtx++) \
        dst4[mtx] = *(const uint4*)(gsrc[mtx] + (size_t)lr*K + (kc) + lc8); }

#define STORE_CHUNK(bufbase, src4) { \
    _Pragma("unroll") \
    for (int mtx = 0; mtx < 4; mtx++) \
        *(uint4*)(bufbase + mtx*MAT + lr*LDT + lc8) = src4[mtx]; }

    {
        uint4 v[4];
        LOAD_CHUNK(v, 0);
        STORE_CHUNK(sm_tc, v);
    }
    __syncthreads();

    const int NC = K >> 5;
    for (int c = 0; c < NC; c++) {
        const bool more = (c + 1 < NC);
        uint4 v[4];
        if (more) LOAD_CHUNK(v, (c + 1) * 32);

        {
            const __nv_bfloat16* buf = sm_tc + (size_t)(c & 1) * 4 * MAT;
            const __nv_bfloat16* sAh = buf;
            const __nv_bfloat16* sAl = buf + MAT;
            const __nv_bfloat16* sWh = buf + 2*MAT;
            const __nv_bfloat16* sWl = buf + 3*MAT;
#pragma unroll
            for (int kf = 0; kf < 2; kf++) {
                const int k0 = kf * 16;
                wmma::fragment<wmma::matrix_a, 16,16,16, __nv_bfloat16, wmma::row_major> ah[2], al[2];
                wmma::fragment<wmma::matrix_b, 16,16,16, __nv_bfloat16, wmma::col_major> bh[2], bl[2];
#pragma unroll
                for (int i = 0; i < 2; i++) {
                    int rbase = (wm*32 + i*16) * LDT + k0;
                    wmma::load_matrix_sync(ah[i], sAh + rbase, LDT);
                    wmma::load_matrix_sync(al[i], sAl + rbase, LDT);
                }
#pragma unroll
                for (int j = 0; j < 2; j++) {
                    int nbase = (wn*32 + j*16) * LDT + k0;
                    wmma::load_matrix_sync(bh[j], sWh + nbase, LDT);
                    wmma::load_matrix_sync(bl[j], sWl + nbase, LDT);
                }
#pragma unroll
                for (int i = 0; i < 2; i++)
#pragma unroll
                    for (int j = 0; j < 2; j++) {
                        wmma::mma_sync(acc[i][j], ah[i], bh[j], acc[i][j]);
                        wmma::mma_sync(acc[i][j], ah[i], bl[j], acc[i][j]);
                        wmma::mma_sync(acc[i][j], al[i], bh[j], acc[i][j]);
                    }
            }
        }
        if (more) {
            __nv_bfloat16* buf = sm_tc + (size_t)((c + 1) & 1) * 4 * MAT;
            STORE_CHUNK(buf, v);
        }
        __syncthreads();
    }

    // epilogue: stage frags through per-warp smem, add bias, scale, store
    float* ep = (float*)sm_tc + wid * (16*20);
    const int lane = tid & 31;
#pragma unroll
    for (int i = 0; i < 2; i++) {
#pragma unroll
        for (int j = 0; j < 2; j++) {
            wmma::store_matrix_sync(ep, acc[i][j], 20, wmma::mem_row_major);
            __syncwarp();
#pragma unroll
            for (int e = 0; e < 8; e++) {
                int idx = lane * 8 + e;
                int r = idx >> 4, cc = idx & 15;
                int m = m0 + wm*32 + i*16 + r;
                int n = n0 + wn*32 + j*16 + cc;
                float v = (ep[r*20 + cc] + bias[n]) * scale;
                if (OMODE == 0) {
                    C[(size_t)m * N + n] = v;
                } else {
                    Cf[(size_t)m * N + n] = __float2half_rn(v);
                }
            }
            __syncwarp();
        }
    }
}

// ---------------------------------------------------------------------------
// Tensor-core GEMM, fp32 out, bf16-split inputs -- output projection.
// Same as sgemm_bs<0> but with split-bf16 A operand supplied by flash.
// (sgemm_bs handles it; kept single template.)
// ---------------------------------------------------------------------------

// ---------------------------------------------------------------------------
// Flash attention, fp16 single-term, 512 threads = 16 warps. (R8 proven)
// ---------------------------------------------------------------------------
#define LDQ 72
#define LDK 72
#define LDSF 136
#define OFF_Q  0
#define OFF_K  9216
#define OFF_V  27648
#define OFF_S  46080
#define OFF_L  80896
#define FL_SMEM 81152

__global__ __launch_bounds__(512) void flash_f16(
    const __half* __restrict__ Qf, const __half* __restrict__ Kf,
    const __half* __restrict__ Vf, const float* __restrict__ mask,
    __nv_bfloat16* __restrict__ AOh, __nv_bfloat16* __restrict__ AOl)
{
    extern __shared__ char smraw[];
    __half* sQ = (__half*)(smraw + OFF_Q);
    __half* sK = (__half*)(smraw + OFF_K);
    __half* sV = (__half*)(smraw + OFF_V);
    float*  sS = (float*)(smraw + OFF_S);
    __half* sP = (__half*)(smraw + OFF_S);
    float*  sO = (float*)(smraw + OFF_S);
    float*  sL = (float*)(smraw + OFF_L);

    const int tid = threadIdx.x;
    const int t0 = blockIdx.x * 64;
    const int h  = blockIdx.y;
    const int b  = blockIdx.z;
    const int wid = tid >> 5;
    const int wm = wid >> 3, wn = wid & 7;
    const int wm2 = wid >> 2, wn2 = wid & 3;
    const int srow = tid >> 3;
    const int sc   = (tid & 7) * 16;

    {
        const __half* q = Qf + ((size_t)(b*TT + t0)) * EE + h*HD;
        int r = tid >> 3, c8 = (tid & 7) * 8;
        *(uint4*)&sQ[r*LDQ + c8] = *(const uint4*)(q + (size_t)r*EE + c8);
        if (tid < 64) sL[tid] = 0.f;
    }

    wmma::fragment<wmma::accumulator, 16, 16, 16, float> oacc;
    wmma::fill_fragment(oacc, 0.f);

    const __half* kb = Kf + (size_t)b * SS * EE + h*HD;
    const __half* vb = Vf + (size_t)b * SS * EE + h*HD;
    const float* mrow = mask + ((size_t)(b*TT + t0 + srow)) * TT + sc;

    for (int st = 0; st < SS/128; st++) {
        const int sb = st * 128;
        const int s0b = sb & (TT - 1);

        __syncthreads();
#pragma unroll
        for (int t = 0; t < 2; t++) {
            int slot = tid + t*512;
            int r = slot >> 3, c8 = (slot & 7) * 8;
            size_t go = (size_t)(sb + r) * EE + c8;
            *(uint4*)&sK[r*LDK + c8] = *(const uint4*)(kb + go);
            *(uint4*)&sV[r*LDK + c8] = *(const uint4*)(vb + go);
        }
        __syncthreads();

        {
            wmma::fragment<wmma::accumulator, 16, 16, 16, float> sacc[2];
            wmma::fill_fragment(sacc[0], 0.f);
            wmma::fill_fragment(sacc[1], 0.f);
#pragma unroll
            for (int k = 0; k < 4; k++) {
                wmma::fragment<wmma::matrix_a, 16,16,16, __half, wmma::row_major> af[2];
                wmma::fragment<wmma::matrix_b, 16,16,16, __half, wmma::col_major> bf;
#pragma unroll
                for (int i = 0; i < 2; i++)
                    wmma::load_matrix_sync(af[i], sQ + (wm*32 + i*16)*LDQ + k*16, LDQ);
                wmma::load_matrix_sync(bf, sK + (wn*16)*LDK + k*16, LDK);
#pragma unroll
                for (int i = 0; i < 2; i++)
                    wmma::mma_sync(sacc[i], af[i], bf, sacc[i]);
            }
#pragma unroll
            for (int i = 0; i < 2; i++)
                wmma::store_matrix_sync(sS + (wm*32 + i*16)*LDSF + wn*16,
                                        sacc[i], LDSF, wmma::mem_row_major);
        }
        __syncthreads();

        {
            float p[16];
            const float* mr = mrow + s0b;
            float ls = 0.f;
#pragma unroll
            for (int jv = 0; jv < 4; jv++) {
                float4 mv = *(const float4*)(mr + jv*4);
                float e0 = __expf(sS[srow*LDSF + sc + jv*4 + 0] + mv.x);
                float e1 = __expf(sS[srow*LDSF + sc + jv*4 + 1] + mv.y);
                float e2 = __expf(sS[srow*LDSF + sc + jv*4 + 2] + mv.z);
                float e3 = __expf(sS[srow*LDSF + sc + jv*4 + 3] + mv.w);
                p[jv*4+0] = e0; p[jv*4+1] = e1; p[jv*4+2] = e2; p[jv*4+3] = e3;
                ls += e0 + e1 + e2 + e3;
            }
            ls += __shfl_xor_sync(0xffffffffu, ls, 1);
            ls += __shfl_xor_sync(0xffffffffu, ls, 2);
            ls += __shfl_xor_sync(0xffffffffu, ls, 4);
            __syncthreads();
#pragma unroll
            for (int k2 = 0; k2 < 8; k2++) {
                __half2 pr = __floats2half2_rn(p[2*k2], p[2*k2+1]);
                *(__half2*)&sP[srow*LDSF + sc + 2*k2] = pr;
            }
            if ((tid & 7) == 0) sL[srow] += ls;
        }
        __syncthreads();

#pragma unroll
        for (int k = 0; k < 8; k++) {
            wmma::fragment<wmma::matrix_b, 16,16,16, __half, wmma::row_major> vf;
            wmma::load_matrix_sync(vf, sV + (k*16)*LDK + wn2*16, LDK);
            wmma::fragment<wmma::matrix_a, 16,16,16, __half, wmma::row_major> pf;
            wmma::load_matrix_sync(pf, sP + (wm2*16)*LDSF + k*16, LDSF);
            wmma::mma_sync(oacc, pf, vf, oacc);
        }
    }

    __syncthreads();
    wmma::store_matrix_sync(sO + (wm2*16)*LDQ + wn2*16, oacc, LDQ, wmma::mem_row_major);
    __syncthreads();

    {
        const int r = tid >> 3;
        const int c8 = (tid & 7) * 8;
        const float inv = 1.f / sL[r];
        size_t go = ((size_t)(b*TT + t0 + r)) * EE + h*HD + c8;
#pragma unroll
        for (int v = 0; v < 2; v++) {
            float4 o = *(const float4*)&sO[r*LDQ + c8 + v*4];
            float f[4] = {o.x*inv, o.y*inv, o.z*inv, o.w*inv};
#pragma unroll
            for (int e = 0; e < 2; e++) {
                float a0 = f[2*e], a1 = f[2*e+1];
                __nv_bfloat16 h0 = __float2bfloat16(a0);
                __nv_bfloat16 h1 = __float2bfloat16(a1);
                __nv_bfloat162 hi; hi.x = h0; hi.y = h1;
                __nv_bfloat162 lo;
                lo.x = __float2bfloat16(a0 - __bfloat162float(h0));
                lo.y = __float2bfloat16(a1 - __bfloat162float(h1));
                *(__nv_bfloat162*)(AOh + go + v*4 + e*2) = hi;
                *(__nv_bfloat162*)(AOl + go + v*4 + e*2) = lo;
            }
        }
    }
}

// ---------------------------------------------------------------------------
extern "C" void kernel_launch(void* const* d_in, const int* in_sizes, int n_in,
                              void* d_out, int out_size) {
    const float* x    = (const float*)d_in[0];
    const float* mask = (const float*)d_in[1];
    const float* Wq   = (const float*)d_in[2];
    const float* bq   = (const float*)d_in[3];
    const float* Wk   = (const float*)d_in[4];
    const float* bk   = (const float*)d_in[5];
    const float* Wv   = (const float*)d_in[6];
    const float* bv   = (const float*)d_in[7];
    const float* Wo   = (const float*)d_in[8];
    const float* bo   = (const float*)d_in[9];
    float* out = (float*)d_out;

    __nv_bfloat16 *xh, *xl, *Wqh, *Wql, *Wkh, *Wkl, *Wvh, *Wvl, *Woh, *Wol;
    __nv_bfloat16 *AOhp, *AOlp;
    __half *Qfp, *Kfp, *Vfp;
    cudaGetSymbolAddress((void**)&xh, g_xh);   cudaGetSymbolAddress((void**)&xl, g_xl);
    cudaGetSymbolAddress((void**)&Wqh, g_Wqh); cudaGetSymbolAddress((void**)&Wql, g_Wql);
    cudaGetSymbolAddress((void**)&Wkh, g_Wkh); cudaGetSymbolAddress((void**)&Wkl, g_Wkl);
    cudaGetSymbolAddress((void**)&Wvh, g_Wvh); cudaGetSymbolAddress((void**)&Wvl, g_Wvl);
    cudaGetSymbolAddress((void**)&Woh, g_Woh); cudaGetSymbolAddress((void**)&Wol, g_Wol);
    cudaGetSymbolAddress((void**)&Qfp, g_Qf);
    cudaGetSymbolAddress((void**)&Kfp, g_Kf);
    cudaGetSymbolAddress((void**)&Vfp, g_Vf);
    cudaGetSymbolAddress((void**)&AOhp, g_AOh); cudaGetSymbolAddress((void**)&AOlp, g_AOl);

    static bool attr_done = false;
    if (!attr_done) {
        cudaFuncSetAttribute(sgemm_bs<0>, cudaFuncAttributeMaxDynamicSharedMemorySize, SG_SMEM);
        cudaFuncSetAttribute(sgemm_bs<2>, cudaFuncAttributeMaxDynamicSharedMemorySize, SG_SMEM);
        cudaFuncSetAttribute(flash_f16, cudaFuncAttributeMaxDynamicSharedMemorySize, FL_SMEM);
        attr_done = true;
    }

    // 1) pre-split inputs to bf16 hi/lo
    {
        int nx = BB*TT*EE/4;
        split_f32<<<(nx+255)/256, 256>>>(x, xh, xl, nx);
        int nw1 = EE*EE/4;
        split_f32<<<(nw1+255)/256, 256>>>(Wq, Wqh, Wql, nw1);
        split_f32<<<(nw1+255)/256, 256>>>(Wo, Woh, Wol, nw1);
        int nw2 = MULT*EE*EE/4;
        split_f32<<<(nw2+255)/256, 256>>>(Wk, Wkh, Wkl, nw2);
        split_f32<<<(nw2+255)/256, 256>>>(Wv, Wvh, Wvl, nw2);
    }

    dim3 blk(512);
    // 2) projections (bf16-split GEMMs, fp16-single outputs for flash)
    sgemm_bs<2><<<dim3(EE/128, (BB*TT)/128), blk, SG_SMEM>>>(
        xh, xl, Wqh, Wql, bq, nullptr, Qfp, EE, EE, QSCALE);
    sgemm_bs<2><<<dim3((MULT*EE)/128, (BB*TT)/128), blk, SG_SMEM>>>(
        xh, xl, Wkh, Wkl, bk, nullptr, Kfp, MULT*EE, EE, 1.f);
    sgemm_bs<2><<<dim3((MULT*EE)/128, (BB*TT)/128), blk, SG_SMEM>>>(
        xh, xl, Wvh, Wvl, bv, nullptr, Vfp, MULT*EE, EE, 1.f);
    // 3) flash attention (fp16 single) -> split bf16 AO
    flash_f16<<<dim3(TT/64, HH, BB), dim3(512), FL_SMEM>>>(
        Qfp, Kfp, Vfp, mask, AOhp, AOlp);
    // 4) output projection (bf16 3-term, fp32 out)
    sgemm_bs<0><<<dim3(EE/128, (BB*TT)/128), blk, SG_SMEM>>>(
        AOhp, AOlp, Woh, Wol, bo, out, nullptr, EE, EE, 1.f);
}

// round 10
// speedup vs baseline: 5.2165x; 1.2535x over previous
#include <cuda_runtime.h>
#include <cuda_bf16.h>
#include <cuda_fp16.h>
#include <mma.h>
#include <cstdint>

using namespace nvcuda;

// Problem constants
#define BB 4
#define TT 1024
#define EE 1024
#define HH 16
#define HD 64
#define MULT 2
#define SS (TT*MULT)
static constexpr float QSCALE = 0.125f;  // HD^-0.5

// Scratch (allocation-free rule: __device__ globals)
__device__ __half g_xf[BB*TT*EE];              // fp16 x
__device__ __half g_Wqf[EE*EE];
__device__ __half g_Wkf[MULT*EE*EE];
__device__ __half g_Wvf[MULT*EE*EE];
__device__ __nv_bfloat16 g_Woh[EE*EE], g_Wol[EE*EE];
__device__ __half g_Qf[BB*TT*EE];              // fp16 scaled q
__device__ __half g_Kf[BB*SS*EE];
__device__ __half g_Vf[BB*SS*EE];
__device__ __nv_bfloat16 g_AOh[BB*TT*EE], g_AOl[BB*TT*EE];

// ---------------------------------------------------------------------------
// Elementwise converters
// ---------------------------------------------------------------------------
__global__ __launch_bounds__(256) void cvt_f16(
    const float* __restrict__ src, __half* __restrict__ dst, int n4)
{
    int i = blockIdx.x * blockDim.x + threadIdx.x;
    if (i >= n4) return;
    float4 v = ((const float4*)src)[i];
    ((__half2*)dst)[i*2]   = __floats2half2_rn(v.x, v.y);
    ((__half2*)dst)[i*2+1] = __floats2half2_rn(v.z, v.w);
}

__global__ __launch_bounds__(256) void split_f32(
    const float* __restrict__ src, __nv_bfloat16* __restrict__ h,
    __nv_bfloat16* __restrict__ l, int n4)
{
    int i = blockIdx.x * blockDim.x + threadIdx.x;
    if (i >= n4) return;
    float4 v = ((const float4*)src)[i];
    __nv_bfloat16 h0 = __float2bfloat16(v.x);
    __nv_bfloat16 h1 = __float2bfloat16(v.y);
    __nv_bfloat16 h2 = __float2bfloat16(v.z);
    __nv_bfloat16 h3 = __float2bfloat16(v.w);
    __nv_bfloat162 hh0; hh0.x = h0; hh0.y = h1;
    __nv_bfloat162 hh1; hh1.x = h2; hh1.y = h3;
    __nv_bfloat162 ll0, ll1;
    ll0.x = __float2bfloat16(v.x - __bfloat162float(h0));
    ll0.y = __float2bfloat16(v.y - __bfloat162float(h1));
    ll1.x = __float2bfloat16(v.z - __bfloat162float(h2));
    ll1.y = __float2bfloat16(v.w - __bfloat162float(h3));
    ((__nv_bfloat162*)h)[i*2]   = hh0;
    ((__nv_bfloat162*)h)[i*2+1] = hh1;
    ((__nv_bfloat162*)l)[i*2]   = ll0;
    ((__nv_bfloat162*)l)[i*2+1] = ll1;
}

// ---------------------------------------------------------------------------
// fp16 single-term GEMM (fp32 accum):  C = (A W^T + bias) * scale, fp16 out.
// Tile 128x128, k-chunk 32, double-buffered. 512 threads = 16 warps (4x4),
// warp tile 32x32. Smem 40 KB -> 2 CTAs/SM.
// ---------------------------------------------------------------------------
#define LDH 40
#define MATH_ (128*LDH)
#define SH_SMEM (2*2*MATH_*2)

__global__ __launch_bounds__(512, 2) void sgemm_f16(
    const __half* __restrict__ A, const __half* __restrict__ W,
    const float* __restrict__ bias, __half* __restrict__ Cf,
    int N, int K, float scale)
{
    extern __shared__ __half smh[];

    const int tid = threadIdx.x;
    const int m0 = blockIdx.y * 128;
    const int n0 = blockIdx.x * 128;
    const int wid = tid >> 5;
    const int wm = wid >> 2;
    const int wn = wid & 3;

    wmma::fragment<wmma::accumulator, 16, 16, 16, float> acc[2][2];
#pragma unroll
    for (int i = 0; i < 2; i++)
#pragma unroll
        for (int j = 0; j < 2; j++) wmma::fill_fragment(acc[i][j], 0.f);

    const __half* gsrc[2];
    gsrc[0] = A + (size_t)m0 * K;
    gsrc[1] = W + (size_t)n0 * K;
    const int lr  = tid >> 2;            // row 0..127
    const int lc8 = (tid & 3) * 8;       // col 0/8/16/24

#define H_LOAD(dst4, kc) { \
    _Pragma("unroll") \
    for (int mtx = 0; mtx < 2; mtx++) \
        dst4[mtx] = *(const uint4*)(gsrc[mtx] + (size_t)lr*K + (kc) + lc8); }

#define H_STORE(bufbase, src4) { \
    _Pragma("unroll") \
    for (int mtx = 0; mtx < 2; mtx++) \
        *(uint4*)(bufbase + mtx*MATH_ + lr*LDH + lc8) = src4[mtx]; }

    {
        uint4 v[2];
        H_LOAD(v, 0);
        H_STORE(smh, v);
    }
    __syncthreads();

    const int NC = K >> 5;
    for (int c = 0; c < NC; c++) {
        const bool more = (c + 1 < NC);
        uint4 v[2];
        if (more) H_LOAD(v, (c + 1) * 32);

        {
            const __half* buf = smh + (size_t)(c & 1) * 2 * MATH_;
            const __half* sA = buf;
            const __half* sW = buf + MATH_;
#pragma unroll
            for (int kf = 0; kf < 2; kf++) {
                const int k0 = kf * 16;
                wmma::fragment<wmma::matrix_a, 16,16,16, __half, wmma::row_major> af[2];
                wmma::fragment<wmma::matrix_b, 16,16,16, __half, wmma::col_major> bf[2];
#pragma unroll
                for (int i = 0; i < 2; i++)
                    wmma::load_matrix_sync(af[i], sA + (wm*32 + i*16)*LDH + k0, LDH);
#pragma unroll
                for (int j = 0; j < 2; j++)
                    wmma::load_matrix_sync(bf[j], sW + (wn*32 + j*16)*LDH + k0, LDH);
#pragma unroll
                for (int i = 0; i < 2; i++)
#pragma unroll
                    for (int j = 0; j < 2; j++)
                        wmma::mma_sync(acc[i][j], af[i], bf[j], acc[i][j]);
            }
        }
        if (more) {
            __half* buf = smh + (size_t)((c + 1) & 1) * 2 * MATH_;
            H_STORE(buf, v);
        }
        __syncthreads();
    }

    // epilogue: stage frags through per-warp smem, add bias, scale, fp16 out
    float* ep = (float*)smh + wid * (16*20);
    const int lane = tid & 31;
#pragma unroll
    for (int i = 0; i < 2; i++) {
#pragma unroll
        for (int j = 0; j < 2; j++) {
            wmma::store_matrix_sync(ep, acc[i][j], 20, wmma::mem_row_major);
            __syncwarp();
#pragma unroll
            for (int e = 0; e < 8; e++) {
                int idx = lane * 8 + e;
                int r = idx >> 4, cc = idx & 15;
                int m = m0 + wm*32 + i*16 + r;
                int n = n0 + wn*32 + j*16 + cc;
                Cf[(size_t)m * N + n] =
                    __float2half_rn((ep[r*20 + cc] + bias[n]) * scale);
            }
            __syncwarp();
        }
    }
}

// ---------------------------------------------------------------------------
// bf16 3-term GEMM (output projection, fp32 out). 512 threads = 16 warps.
// ---------------------------------------------------------------------------
#define LDT 40
#define MAT (128*LDT)
#define SG_SMEM (2*4*MAT*2)

__global__ __launch_bounds__(512) void sgemm_bs(
    const __nv_bfloat16* __restrict__ Ah, const __nv_bfloat16* __restrict__ Al,
    const __nv_bfloat16* __restrict__ Wh, const __nv_bfloat16* __restrict__ Wl,
    const float* __restrict__ bias, float* __restrict__ C,
    int N, int K, float scale)
{
    extern __shared__ __nv_bfloat16 sm_tc[];

    const int tid = threadIdx.x;
    const int m0 = blockIdx.y * 128;
    const int n0 = blockIdx.x * 128;
    const int wid = tid >> 5;
    const int wm = wid >> 2;
    const int wn = wid & 3;

    wmma::fragment<wmma::accumulator, 16, 16, 16, float> acc[2][2];
#pragma unroll
    for (int i = 0; i < 2; i++)
#pragma unroll
        for (int j = 0; j < 2; j++) wmma::fill_fragment(acc[i][j], 0.f);

    const __nv_bfloat16* gsrc[4];
    gsrc[0] = Ah + (size_t)m0 * K; gsrc[1] = Al + (size_t)m0 * K;
    gsrc[2] = Wh + (size_t)n0 * K; gsrc[3] = Wl + (size_t)n0 * K;
    const int lr  = tid >> 2;
    const int lc8 = (tid & 3) * 8;

#define LOAD_CHUNK(dst4, kc) { \
    _Pragma("unroll") \
    for (int mtx = 0; mtx < 4; mtx++) \
        dst4[mtx] = *(const uint4*)(gsrc[mtx] + (size_t)lr*K + (kc) + lc8); }

#define STORE_CHUNK(bufbase, src4) { \
    _Pragma("unroll") \
    for (int mtx = 0; mtx < 4; mtx++) \
        *(uint4*)(bufbase + mtx*MAT + lr*LDT + lc8) = src4[mtx]; }

    {
        uint4 v[4];
        LOAD_CHUNK(v, 0);
        STORE_CHUNK(sm_tc, v);
    }
    __syncthreads();

    const int NC = K >> 5;
    for (int c = 0; c < NC; c++) {
        const bool more = (c + 1 < NC);
        uint4 v[4];
        if (more) LOAD_CHUNK(v, (c + 1) * 32);

        {
            const __nv_bfloat16* buf = sm_tc + (size_t)(c & 1) * 4 * MAT;
            const __nv_bfloat16* sAh = buf;
            const __nv_bfloat16* sAl = buf + MAT;
            const __nv_bfloat16* sWh = buf + 2*MAT;
            const __nv_bfloat16* sWl = buf + 3*MAT;
#pragma unroll
            for (int kf = 0; kf < 2; kf++) {
                const int k0 = kf * 16;
                wmma::fragment<wmma::matrix_a, 16,16,16, __nv_bfloat16, wmma::row_major> ah[2], al[2];
                wmma::fragment<wmma::matrix_b, 16,16,16, __nv_bfloat16, wmma::col_major> bh[2], bl[2];
#pragma unroll
                for (int i = 0; i < 2; i++) {
                    int rbase = (wm*32 + i*16) * LDT + k0;
                    wmma::load_matrix_sync(ah[i], sAh + rbase, LDT);
                    wmma::load_matrix_sync(al[i], sAl + rbase, LDT);
                }
#pragma unroll
                for (int j = 0; j < 2; j++) {
                    int nbase = (wn*32 + j*16) * LDT + k0;
                    wmma::load_matrix_sync(bh[j], sWh + nbase, LDT);
                    wmma::load_matrix_sync(bl[j], sWl + nbase, LDT);
                }
#pragma unroll
                for (int i = 0; i < 2; i++)
#pragma unroll
                    for (int j = 0; j < 2; j++) {
                        wmma::mma_sync(acc[i][j], ah[i], bh[j], acc[i][j]);
                        wmma::mma_sync(acc[i][j], ah[i], bl[j], acc[i][j]);
                        wmma::mma_sync(acc[i][j], al[i], bh[j], acc[i][j]);
                    }
            }
        }
        if (more) {
            __nv_bfloat16* buf = sm_tc + (size_t)((c + 1) & 1) * 4 * MAT;
            STORE_CHUNK(buf, v);
        }
        __syncthreads();
    }

    float* ep = (float*)sm_tc + wid * (16*20);
    const int lane = tid & 31;
#pragma unroll
    for (int i = 0; i < 2; i++) {
#pragma unroll
        for (int j = 0; j < 2; j++) {
            wmma::store_matrix_sync(ep, acc[i][j], 20, wmma::mem_row_major);
            __syncwarp();
#pragma unroll
            for (int e = 0; e < 8; e++) {
                int idx = lane * 8 + e;
                int r = idx >> 4, cc = idx & 15;
                int m = m0 + wm*32 + i*16 + r;
                int n = n0 + wn*32 + j*16 + cc;
                C[(size_t)m * N + n] = (ep[r*20 + cc] + bias[n]) * scale;
            }
            __syncwarp();
        }
    }
}

// ---------------------------------------------------------------------------
// Flash attention, fp16 single-term, 512 threads = 16 warps. (R8 proven)
// ---------------------------------------------------------------------------
#define LDQ 72
#define LDK 72
#define LDSF 136
#define OFF_Q  0
#define OFF_K  9216
#define OFF_V  27648
#define OFF_S  46080
#define OFF_L  80896
#define FL_SMEM 81152

__global__ __launch_bounds__(512) void flash_f16(
    const __half* __restrict__ Qf, const __half* __restrict__ Kf,
    const __half* __restrict__ Vf, const float* __restrict__ mask,
    __nv_bfloat16* __restrict__ AOh, __nv_bfloat16* __restrict__ AOl)
{
    extern __shared__ char smraw[];
    __half* sQ = (__half*)(smraw + OFF_Q);
    __half* sK = (__half*)(smraw + OFF_K);
    __half* sV = (__half*)(smraw + OFF_V);
    float*  sS = (float*)(smraw + OFF_S);
    __half* sP = (__half*)(smraw + OFF_S);
    float*  sO = (float*)(smraw + OFF_S);
    float*  sL = (float*)(smraw + OFF_L);

    const int tid = threadIdx.x;
    const int t0 = blockIdx.x * 64;
    const int h  = blockIdx.y;
    const int b  = blockIdx.z;
    const int wid = tid >> 5;
    const int wm = wid >> 3, wn = wid & 7;
    const int wm2 = wid >> 2, wn2 = wid & 3;
    const int srow = tid >> 3;
    const int sc   = (tid & 7) * 16;

    {
        const __half* q = Qf + ((size_t)(b*TT + t0)) * EE + h*HD;
        int r = tid >> 3, c8 = (tid & 7) * 8;
        *(uint4*)&sQ[r*LDQ + c8] = *(const uint4*)(q + (size_t)r*EE + c8);
        if (tid < 64) sL[tid] = 0.f;
    }

    wmma::fragment<wmma::accumulator, 16, 16, 16, float> oacc;
    wmma::fill_fragment(oacc, 0.f);

    const __half* kb = Kf + (size_t)b * SS * EE + h*HD;
    const __half* vb = Vf + (size_t)b * SS * EE + h*HD;
    const float* mrow = mask + ((size_t)(b*TT + t0 + srow)) * TT + sc;

    for (int st = 0; st < SS/128; st++) {
        const int sb = st * 128;
        const int s0b = sb & (TT - 1);

        __syncthreads();
#pragma unroll
        for (int t = 0; t < 2; t++) {
            int slot = tid + t*512;
            int r = slot >> 3, c8 = (slot & 7) * 8;
            size_t go = (size_t)(sb + r) * EE + c8;
            *(uint4*)&sK[r*LDK + c8] = *(const uint4*)(kb + go);
            *(uint4*)&sV[r*LDK + c8] = *(const uint4*)(vb + go);
        }
        __syncthreads();

        {
            wmma::fragment<wmma::accumulator, 16, 16, 16, float> sacc[2];
            wmma::fill_fragment(sacc[0], 0.f);
            wmma::fill_fragment(sacc[1], 0.f);
#pragma unroll
            for (int k = 0; k < 4; k++) {
                wmma::fragment<wmma::matrix_a, 16,16,16, __half, wmma::row_major> af[2];
                wmma::fragment<wmma::matrix_b, 16,16,16, __half, wmma::col_major> bf;
#pragma unroll
                for (int i = 0; i < 2; i++)
                    wmma::load_matrix_sync(af[i], sQ + (wm*32 + i*16)*LDQ + k*16, LDQ);
                wmma::load_matrix_sync(bf, sK + (wn*16)*LDK + k*16, LDK);
#pragma unroll
                for (int i = 0; i < 2; i++)
                    wmma::mma_sync(sacc[i], af[i], bf, sacc[i]);
            }
#pragma unroll
            for (int i = 0; i < 2; i++)
                wmma::store_matrix_sync(sS + (wm*32 + i*16)*LDSF + wn*16,
                                        sacc[i], LDSF, wmma::mem_row_major);
        }
        __syncthreads();

        {
            float p[16];
            const float* mr = mrow + s0b;
            float ls = 0.f;
#pragma unroll
            for (int jv = 0; jv < 4; jv++) {
                float4 mv = *(const float4*)(mr + jv*4);
                float e0 = __expf(sS[srow*LDSF + sc + jv*4 + 0] + mv.x);
                float e1 = __expf(sS[srow*LDSF + sc + jv*4 + 1] + mv.y);
                float e2 = __expf(sS[srow*LDSF + sc + jv*4 + 2] + mv.z);
                float e3 = __expf(sS[srow*LDSF + sc + jv*4 + 3] + mv.w);
                p[jv*4+0] = e0; p[jv*4+1] = e1; p[jv*4+2] = e2; p[jv*4+3] = e3;
                ls += e0 + e1 + e2 + e3;
            }
            ls += __shfl_xor_sync(0xffffffffu, ls, 1);
            ls += __shfl_xor_sync(0xffffffffu, ls, 2);
            ls += __shfl_xor_sync(0xffffffffu, ls, 4);
            __syncthreads();
#pragma unroll
            for (int k2 = 0; k2 < 8; k2++) {
                __half2 pr = __floats2half2_rn(p[2*k2], p[2*k2+1]);
                *(__half2*)&sP[srow*LDSF + sc + 2*k2] = pr;
            }
            if ((tid & 7) == 0) sL[srow] += ls;
        }
        __syncthreads();

#pragma unroll
        for (int k = 0; k < 8; k++) {
            wmma::fragment<wmma::matrix_b, 16,16,16, __half, wmma::row_major> vf;
            wmma::load_matrix_sync(vf, sV + (k*16)*LDK + wn2*16, LDK);
            wmma::fragment<wmma::matrix_a, 16,16,16, __half, wmma::row_major> pf;
            wmma::load_matrix_sync(pf, sP + (wm2*16)*LDSF + k*16, LDSF);
            wmma::mma_sync(oacc, pf, vf, oacc);
        }
    }

    __syncthreads();
    wmma::store_matrix_sync(sO + (wm2*16)*LDQ + wn2*16, oacc, LDQ, wmma::mem_row_major);
    __syncthreads();

    {
        const int r = tid >> 3;
        const int c8 = (tid & 7) * 8;
        const float inv = 1.f / sL[r];
        size_t go = ((size_t)(b*TT + t0 + r)) * EE + h*HD + c8;
#pragma unroll
        for (int v = 0; v < 2; v++) {
            float4 o = *(const float4*)&sO[r*LDQ + c8 + v*4];
            float f[4] = {o.x*inv, o.y*inv, o.z*inv, o.w*inv};
#pragma unroll
            for (int e = 0; e < 2; e++) {
                float a0 = f[2*e], a1 = f[2*e+1];
                __nv_bfloat16 h0 = __float2bfloat16(a0);
                __nv_bfloat16 h1 = __float2bfloat16(a1);
                __nv_bfloat162 hi; hi.x = h0; hi.y = h1;
                __nv_bfloat162 lo;
                lo.x = __float2bfloat16(a0 - __bfloat162float(h0));
                lo.y = __float2bfloat16(a1 - __bfloat162float(h1));
                *(__nv_bfloat162*)(AOh + go + v*4 + e*2) = hi;
                *(__nv_bfloat162*)(AOl + go + v*4 + e*2) = lo;
            }
        }
    }
}

// ---------------------------------------------------------------------------
extern "C" void kernel_launch(void* const* d_in, const int* in_sizes, int n_in,
                              void* d_out, int out_size) {
    const float* x    = (const float*)d_in[0];
    const float* mask = (const float*)d_in[1];
    const float* Wq   = (const float*)d_in[2];
    const float* bq   = (const float*)d_in[3];
    const float* Wk   = (const float*)d_in[4];
    const float* bk   = (const float*)d_in[5];
    const float* Wv   = (const float*)d_in[6];
    const float* bv   = (const float*)d_in[7];
    const float* Wo   = (const float*)d_in[8];
    const float* bo   = (const float*)d_in[9];
    float* out = (float*)d_out;

    __half *xf, *Wqf, *Wkf, *Wvf, *Qfp, *Kfp, *Vfp;
    __nv_bfloat16 *Woh, *Wol, *AOhp, *AOlp;
    cudaGetSymbolAddress((void**)&xf, g_xf);
    cudaGetSymbolAddress((void**)&Wqf, g_Wqf);
    cudaGetSymbolAddress((void**)&Wkf, g_Wkf);
    cudaGetSymbolAddress((void**)&Wvf, g_Wvf);
    cudaGetSymbolAddress((void**)&Woh, g_Woh);
    cudaGetSymbolAddress((void**)&Wol, g_Wol);
    cudaGetSymbolAddress((void**)&Qfp, g_Qf);
    cudaGetSymbolAddress((void**)&Kfp, g_Kf);
    cudaGetSymbolAddress((void**)&Vfp, g_Vf);
    cudaGetSymbolAddress((void**)&AOhp, g_AOh);
    cudaGetSymbolAddress((void**)&AOlp, g_AOl);

    static bool attr_done = false;
    if (!attr_done) {
        cudaFuncSetAttribute(sgemm_f16, cudaFuncAttributeMaxDynamicSharedMemorySize, SH_SMEM);
        cudaFuncSetAttribute(sgemm_bs, cudaFuncAttributeMaxDynamicSharedMemorySize, SG_SMEM);
        cudaFuncSetAttribute(flash_f16, cudaFuncAttributeMaxDynamicSharedMemorySize, FL_SMEM);
        attr_done = true;
    }

    // 1) convert inputs
    {
        int nx = BB*TT*EE/4;
        cvt_f16<<<(nx+255)/256, 256>>>(x, xf, nx);
        int nw1 = EE*EE/4;
        cvt_f16<<<(nw1+255)/256, 256>>>(Wq, Wqf, nw1);
        int nw2 = MULT*EE*EE/4;
        cvt_f16<<<(nw2+255)/256, 256>>>(Wk, Wkf, nw2);
        cvt_f16<<<(nw2+255)/256, 256>>>(Wv, Wvf, nw2);
        split_f32<<<(nw1+255)/256, 256>>>(Wo, Woh, Wol, nw1);
    }

    dim3 blk(512);
    // 2) QKV projections (fp16 single-term GEMMs)
    sgemm_f16<<<dim3(EE/128, (BB*TT)/128), blk, SH_SMEM>>>(
        xf, Wqf, bq, Qfp, EE, EE, QSCALE);
    sgemm_f16<<<dim3((MULT*EE)/128, (BB*TT)/128), blk, SH_SMEM>>>(
        xf, Wkf, bk, Kfp, MULT*EE, EE, 1.f);
    sgemm_f16<<<dim3((MULT*EE)/128, (BB*TT)/128), blk, SH_SMEM>>>(
        xf, Wvf, bv, Vfp, MULT*EE, EE, 1.f);
    // 3) flash attention (fp16 single) -> split bf16 AO
    flash_f16<<<dim3(TT/64, HH, BB), blk, FL_SMEM>>>(
        Qfp, Kfp, Vfp, mask, AOhp, AOlp);
    // 4) output projection (bf16 3-term, fp32 out)
    sgemm_bs<<<dim3(EE/128, (BB*TT)/128), blk, SG_SMEM>>>(
        AOhp, AOlp, Woh, Wol, bo, out, EE, EE, 1.f);
}

// round 11
// speedup vs baseline: 5.5652x; 1.0668x over previous
#include <cuda_runtime.h>
#include <cuda_bf16.h>
#include <cuda_fp16.h>
#include <mma.h>
#include <cstdint>

using namespace nvcuda;

// Problem constants
#define BB 4
#define TT 1024
#define EE 1024
#define HH 16
#define HD 64
#define MULT 2
#define SS (TT*MULT)
static constexpr float QSCALE = 0.125f;  // HD^-0.5

// Scratch (allocation-free rule: __device__ globals)
__device__ __half g_xf[BB*TT*EE];              // fp16 x
__device__ __half g_Wqf[EE*EE];
__device__ __half g_Wkf[MULT*EE*EE];
__device__ __half g_Wvf[MULT*EE*EE];
__device__ __half g_Wof[EE*EE];
__device__ __half g_Qf[BB*TT*EE];              // fp16 scaled q
__device__ __half g_Kf[BB*SS*EE];
__device__ __half g_Vf[BB*SS*EE];
__device__ __half g_AOf[BB*TT*EE];             // fp16 attention output

// ---------------------------------------------------------------------------
// Elementwise fp32 -> fp16 convert. n4 = n/4.
// ---------------------------------------------------------------------------
__global__ __launch_bounds__(256) void cvt_f16(
    const float* __restrict__ src, __half* __restrict__ dst, int n4)
{
    int i = blockIdx.x * blockDim.x + threadIdx.x;
    if (i >= n4) return;
    float4 v = ((const float4*)src)[i];
    ((__half2*)dst)[i*2]   = __floats2half2_rn(v.x, v.y);
    ((__half2*)dst)[i*2+1] = __floats2half2_rn(v.z, v.w);
}

// ---------------------------------------------------------------------------
// fp16 single-term GEMM (fp32 accum):  C = (A W^T + bias) * scale.
// OMODE 0: fp32 out (C). 2: fp16 out (Cf).
// Tile 128x128, k-chunk 32, double-buffered. 512 threads = 16 warps (4x4),
// warp tile 32x32. Smem 40 KB -> 2 CTAs/SM.
// ---------------------------------------------------------------------------
#define LDH 40
#define MATH_ (128*LDH)
#define SH_SMEM (2*2*MATH_*2)

template<int OMODE>
__global__ __launch_bounds__(512, 2) void sgemm_f16(
    const __half* __restrict__ A, const __half* __restrict__ W,
    const float* __restrict__ bias, float* __restrict__ C,
    __half* __restrict__ Cf,
    int N, int K, float scale)
{
    extern __shared__ __half smh[];

    const int tid = threadIdx.x;
    const int m0 = blockIdx.y * 128;
    const int n0 = blockIdx.x * 128;
    const int wid = tid >> 5;
    const int wm = wid >> 2;
    const int wn = wid & 3;

    wmma::fragment<wmma::accumulator, 16, 16, 16, float> acc[2][2];
#pragma unroll
    for (int i = 0; i < 2; i++)
#pragma unroll
        for (int j = 0; j < 2; j++) wmma::fill_fragment(acc[i][j], 0.f);

    const __half* gsrc[2];
    gsrc[0] = A + (size_t)m0 * K;
    gsrc[1] = W + (size_t)n0 * K;
    const int lr  = tid >> 2;            // row 0..127
    const int lc8 = (tid & 3) * 8;       // col 0/8/16/24

#define H_LOAD(dst4, kc) { \
    _Pragma("unroll") \
    for (int mtx = 0; mtx < 2; mtx++) \
        dst4[mtx] = *(const uint4*)(gsrc[mtx] + (size_t)lr*K + (kc) + lc8); }

#define H_STORE(bufbase, src4) { \
    _Pragma("unroll") \
    for (int mtx = 0; mtx < 2; mtx++) \
        *(uint4*)(bufbase + mtx*MATH_ + lr*LDH + lc8) = src4[mtx]; }

    {
        uint4 v[2];
        H_LOAD(v, 0);
        H_STORE(smh, v);
    }
    __syncthreads();

    const int NC = K >> 5;
    for (int c = 0; c < NC; c++) {
        const bool more = (c + 1 < NC);
        uint4 v[2];
        if (more) H_LOAD(v, (c + 1) * 32);

        {
            const __half* buf = smh + (size_t)(c & 1) * 2 * MATH_;
            const __half* sA = buf;
            const __half* sW = buf + MATH_;
#pragma unroll
            for (int kf = 0; kf < 2; kf++) {
                const int k0 = kf * 16;
                wmma::fragment<wmma::matrix_a, 16,16,16, __half, wmma::row_major> af[2];
                wmma::fragment<wmma::matrix_b, 16,16,16, __half, wmma::col_major> bf[2];
#pragma unroll
                for (int i = 0; i < 2; i++)
                    wmma::load_matrix_sync(af[i], sA + (wm*32 + i*16)*LDH + k0, LDH);
#pragma unroll
                for (int j = 0; j < 2; j++)
                    wmma::load_matrix_sync(bf[j], sW + (wn*32 + j*16)*LDH + k0, LDH);
#pragma unroll
                for (int i = 0; i < 2; i++)
#pragma unroll
                    for (int j = 0; j < 2; j++)
                        wmma::mma_sync(acc[i][j], af[i], bf[j], acc[i][j]);
            }
        }
        if (more) {
            __half* buf = smh + (size_t)((c + 1) & 1) * 2 * MATH_;
            H_STORE(buf, v);
        }
        __syncthreads();
    }

    // epilogue: stage frags through per-warp smem, add bias, scale, store
    float* ep = (float*)smh + wid * (16*20);
    const int lane = tid & 31;
#pragma unroll
    for (int i = 0; i < 2; i++) {
#pragma unroll
        for (int j = 0; j < 2; j++) {
            wmma::store_matrix_sync(ep, acc[i][j], 20, wmma::mem_row_major);
            __syncwarp();
#pragma unroll
            for (int e = 0; e < 8; e++) {
                int idx = lane * 8 + e;
                int r = idx >> 4, cc = idx & 15;
                int m = m0 + wm*32 + i*16 + r;
                int n = n0 + wn*32 + j*16 + cc;
                float v = (ep[r*20 + cc] + bias[n]) * scale;
                if (OMODE == 0) {
                    C[(size_t)m * N + n] = v;
                } else {
                    Cf[(size_t)m * N + n] = __float2half_rn(v);
                }
            }
            __syncwarp();
        }
    }
}

// ---------------------------------------------------------------------------
// Flash attention, fp16 single-term, 512 threads = 16 warps. (R8/R10 proven)
// Output: fp16 AO.
// ---------------------------------------------------------------------------
#define LDQ 72
#define LDK 72
#define LDSF 136
#define OFF_Q  0
#define OFF_K  9216
#define OFF_V  27648
#define OFF_S  46080
#define OFF_L  80896
#define FL_SMEM 81152

__global__ __launch_bounds__(512) void flash_f16(
    const __half* __restrict__ Qf, const __half* __restrict__ Kf,
    const __half* __restrict__ Vf, const float* __restrict__ mask,
    __half* __restrict__ AOf)
{
    extern __shared__ char smraw[];
    __half* sQ = (__half*)(smraw + OFF_Q);
    __half* sK = (__half*)(smraw + OFF_K);
    __half* sV = (__half*)(smraw + OFF_V);
    float*  sS = (float*)(smraw + OFF_S);
    __half* sP = (__half*)(smraw + OFF_S);
    float*  sO = (float*)(smraw + OFF_S);
    float*  sL = (float*)(smraw + OFF_L);

    const int tid = threadIdx.x;
    const int t0 = blockIdx.x * 64;
    const int h  = blockIdx.y;
    const int b  = blockIdx.z;
    const int wid = tid >> 5;
    const int wm = wid >> 3, wn = wid & 7;
    const int wm2 = wid >> 2, wn2 = wid & 3;
    const int srow = tid >> 3;
    const int sc   = (tid & 7) * 16;

    {
        const __half* q = Qf + ((size_t)(b*TT + t0)) * EE + h*HD;
        int r = tid >> 3, c8 = (tid & 7) * 8;
        *(uint4*)&sQ[r*LDQ + c8] = *(const uint4*)(q + (size_t)r*EE + c8);
        if (tid < 64) sL[tid] = 0.f;
    }

    wmma::fragment<wmma::accumulator, 16, 16, 16, float> oacc;
    wmma::fill_fragment(oacc, 0.f);

    const __half* kb = Kf + (size_t)b * SS * EE + h*HD;
    const __half* vb = Vf + (size_t)b * SS * EE + h*HD;
    const float* mrow = mask + ((size_t)(b*TT + t0 + srow)) * TT + sc;

    for (int st = 0; st < SS/128; st++) {
        const int sb = st * 128;
        const int s0b = sb & (TT - 1);

        __syncthreads();
#pragma unroll
        for (int t = 0; t < 2; t++) {
            int slot = tid + t*512;
            int r = slot >> 3, c8 = (slot & 7) * 8;
            size_t go = (size_t)(sb + r) * EE + c8;
            *(uint4*)&sK[r*LDK + c8] = *(const uint4*)(kb + go);
            *(uint4*)&sV[r*LDK + c8] = *(const uint4*)(vb + go);
        }
        __syncthreads();

        {
            wmma::fragment<wmma::accumulator, 16, 16, 16, float> sacc[2];
            wmma::fill_fragment(sacc[0], 0.f);
            wmma::fill_fragment(sacc[1], 0.f);
#pragma unroll
            for (int k = 0; k < 4; k++) {
                wmma::fragment<wmma::matrix_a, 16,16,16, __half, wmma::row_major> af[2];
                wmma::fragment<wmma::matrix_b, 16,16,16, __half, wmma::col_major> bf;
#pragma unroll
                for (int i = 0; i < 2; i++)
                    wmma::load_matrix_sync(af[i], sQ + (wm*32 + i*16)*LDQ + k*16, LDQ);
                wmma::load_matrix_sync(bf, sK + (wn*16)*LDK + k*16, LDK);
#pragma unroll
                for (int i = 0; i < 2; i++)
                    wmma::mma_sync(sacc[i], af[i], bf, sacc[i]);
            }
#pragma unroll
            for (int i = 0; i < 2; i++)
                wmma::store_matrix_sync(sS + (wm*32 + i*16)*LDSF + wn*16,
                                        sacc[i], LDSF, wmma::mem_row_major);
        }
        __syncthreads();

        {
            float p[16];
            const float* mr = mrow + s0b;
            float ls = 0.f;
#pragma unroll
            for (int jv = 0; jv < 4; jv++) {
                float4 mv = *(const float4*)(mr + jv*4);
                float e0 = __expf(sS[srow*LDSF + sc + jv*4 + 0] + mv.x);
                float e1 = __expf(sS[srow*LDSF + sc + jv*4 + 1] + mv.y);
                float e2 = __expf(sS[srow*LDSF + sc + jv*4 + 2] + mv.z);
                float e3 = __expf(sS[srow*LDSF + sc + jv*4 + 3] + mv.w);
                p[jv*4+0] = e0; p[jv*4+1] = e1; p[jv*4+2] = e2; p[jv*4+3] = e3;
                ls += e0 + e1 + e2 + e3;
            }
            ls += __shfl_xor_sync(0xffffffffu, ls, 1);
            ls += __shfl_xor_sync(0xffffffffu, ls, 2);
            ls += __shfl_xor_sync(0xffffffffu, ls, 4);
            __syncthreads();
#pragma unroll
            for (int k2 = 0; k2 < 8; k2++) {
                __half2 pr = __floats2half2_rn(p[2*k2], p[2*k2+1]);
                *(__half2*)&sP[srow*LDSF + sc + 2*k2] = pr;
            }
            if ((tid & 7) == 0) sL[srow] += ls;
        }
        __syncthreads();

#pragma unroll
        for (int k = 0; k < 8; k++) {
            wmma::fragment<wmma::matrix_b, 16,16,16, __half, wmma::row_major> vf;
            wmma::load_matrix_sync(vf, sV + (k*16)*LDK + wn2*16, LDK);
            wmma::fragment<wmma::matrix_a, 16,16,16, __half, wmma::row_major> pf;
            wmma::load_matrix_sync(pf, sP + (wm2*16)*LDSF + k*16, LDSF);
            wmma::mma_sync(oacc, pf, vf, oacc);
        }
    }

    __syncthreads();
    wmma::store_matrix_sync(sO + (wm2*16)*LDQ + wn2*16, oacc, LDQ, wmma::mem_row_major);
    __syncthreads();

    // write out fp16: AO[b, t0+r, h*HD + c] = sO / l
    {
        const int r = tid >> 3;
        const int c8 = (tid & 7) * 8;
        const float inv = 1.f / sL[r];
        __half* ob = AOf + ((size_t)(b*TT + t0 + r)) * EE + h*HD + c8;
#pragma unroll
        for (int v = 0; v < 2; v++) {
            float4 o = *(const float4*)&sO[r*LDQ + c8 + v*4];
            __half2 p0 = __floats2half2_rn(o.x*inv, o.y*inv);
            __half2 p1 = __floats2half2_rn(o.z*inv, o.w*inv);
            *(__half2*)(ob + v*4)     = p0;
            *(__half2*)(ob + v*4 + 2) = p1;
        }
    }
}

// ---------------------------------------------------------------------------
extern "C" void kernel_launch(void* const* d_in, const int* in_sizes, int n_in,
                              void* d_out, int out_size) {
    const float* x    = (const float*)d_in[0];
    const float* mask = (const float*)d_in[1];
    const float* Wq   = (const float*)d_in[2];
    const float* bq   = (const float*)d_in[3];
    const float* Wk   = (const float*)d_in[4];
    const float* bk   = (const float*)d_in[5];
    const float* Wv   = (const float*)d_in[6];
    const float* bv   = (const float*)d_in[7];
    const float* Wo   = (const float*)d_in[8];
    const float* bo   = (const float*)d_in[9];
    float* out = (float*)d_out;

    __half *xf, *Wqf, *Wkf, *Wvf, *Wof, *Qfp, *Kfp, *Vfp, *AOfp;
    cudaGetSymbolAddress((void**)&xf, g_xf);
    cudaGetSymbolAddress((void**)&Wqf, g_Wqf);
    cudaGetSymbolAddress((void**)&Wkf, g_Wkf);
    cudaGetSymbolAddress((void**)&Wvf, g_Wvf);
    cudaGetSymbolAddress((void**)&Wof, g_Wof);
    cudaGetSymbolAddress((void**)&Qfp, g_Qf);
    cudaGetSymbolAddress((void**)&Kfp, g_Kf);
    cudaGetSymbolAddress((void**)&Vfp, g_Vf);
    cudaGetSymbolAddress((void**)&AOfp, g_AOf);

    static bool attr_done = false;
    if (!attr_done) {
        cudaFuncSetAttribute(sgemm_f16<0>, cudaFuncAttributeMaxDynamicSharedMemorySize, SH_SMEM);
        cudaFuncSetAttribute(sgemm_f16<2>, cudaFuncAttributeMaxDynamicSharedMemorySize, SH_SMEM);
        cudaFuncSetAttribute(flash_f16, cudaFuncAttributeMaxDynamicSharedMemorySize, FL_SMEM);
        attr_done = true;
    }

    // 1) convert inputs to fp16
    {
        int nx = BB*TT*EE/4;
        cvt_f16<<<(nx+255)/256, 256>>>(x, xf, nx);
        int nw1 = EE*EE/4;
        cvt_f16<<<(nw1+255)/256, 256>>>(Wq, Wqf, nw1);
        cvt_f16<<<(nw1+255)/256, 256>>>(Wo, Wof, nw1);
        int nw2 = MULT*EE*EE/4;
        cvt_f16<<<(nw2+255)/256, 256>>>(Wk, Wkf, nw2);
        cvt_f16<<<(nw2+255)/256, 256>>>(Wv, Wvf, nw2);
    }

    dim3 blk(512);
    // 2) QKV projections (fp16 single-term GEMMs)
    sgemm_f16<2><<<dim3(EE/128, (BB*TT)/128), blk, SH_SMEM>>>(
        xf, Wqf, bq, nullptr, Qfp, EE, EE, QSCALE);
    sgemm_f16<2><<<dim3((MULT*EE)/128, (BB*TT)/128), blk, SH_SMEM>>>(
        xf, Wkf, bk, nullptr, Kfp, MULT*EE, EE, 1.f);
    sgemm_f16<2><<<dim3((MULT*EE)/128, (BB*TT)/128), blk, SH_SMEM>>>(
        xf, Wvf, bv, nullptr, Vfp, MULT*EE, EE, 1.f);
    // 3) flash attention (fp16 single) -> fp16 AO
    flash_f16<<<dim3(TT/64, HH, BB), blk, FL_SMEM>>>(
        Qfp, Kfp, Vfp, mask, AOfp);
    // 4) output projection (fp16 single-term, fp32 out)
    sgemm_f16<0><<<dim3(EE/128, (BB*TT)/128), blk, SH_SMEM>>>(
        AOfp, Wof, bo, out, nullptr, EE, EE, 1.f);
}

// round 12
// speedup vs baseline: 6.6619x; 1.1971x over previous
#include <cuda_runtime.h>
#include <cuda_bf16.h>
#include <cuda_fp16.h>
#include <mma.h>
#include <cstdint>

using namespace nvcuda;

// Problem constants
#define BB 4
#define TT 1024
#define EE 1024
#define HH 16
#define HD 64
#define MULT 2
#define SS (TT*MULT)
static constexpr float QSCALE = 0.125f;  // HD^-0.5

// Scratch (allocation-free rule: __device__ globals)
__device__ __half g_xf[BB*TT*EE];              // fp16 x
__device__ __half g_Wqf[EE*EE];
__device__ __half g_Wkf[MULT*EE*EE];
__device__ __half g_Wvf[MULT*EE*EE];
__device__ __half g_Wof[EE*EE];
__device__ __half g_Qf[BB*TT*EE];              // fp16 scaled q
__device__ __half g_Kf[BB*SS*EE];
__device__ __half g_Vf[BB*SS*EE];
__device__ __half g_AOf[BB*TT*EE];             // fp16 attention output

// ---------------------------------------------------------------------------
// Elementwise fp32 -> fp16 convert. n4 = n/4.
// ---------------------------------------------------------------------------
__global__ __launch_bounds__(256) void cvt_f16(
    const float* __restrict__ src, __half* __restrict__ dst, int n4)
{
    int i = blockIdx.x * blockDim.x + threadIdx.x;
    if (i >= n4) return;
    float4 v = ((const float4*)src)[i];
    ((__half2*)dst)[i*2]   = __floats2half2_rn(v.x, v.y);
    ((__half2*)dst)[i*2+1] = __floats2half2_rn(v.z, v.w);
}

// ---------------------------------------------------------------------------
// fp16 single-term GEMM (fp32 accum):  C = (A W^T + bias) * scale.
// OMODE 0: fp32 out (C). 2: fp16 out (Cf).
// Tile 128x128, k-chunk 32, double-buffered. 256 threads = 8 warps in 4x2
// grid; warp tile 32x64 (acc[2][4]); B frag streamed (1 live) for density.
// Smem 40 KB -> 2 CTAs/SM.
// ---------------------------------------------------------------------------
#define LDH 40
#define MATH_ (128*LDH)
#define SH_SMEM (2*2*MATH_*2)

template<int OMODE>
__global__ __launch_bounds__(256, 2) void sgemm_f16(
    const __half* __restrict__ A, const __half* __restrict__ W,
    const float* __restrict__ bias, float* __restrict__ C,
    __half* __restrict__ Cf,
    int N, int K, float scale)
{
    extern __shared__ __half smh[];

    const int tid = threadIdx.x;
    const int m0 = blockIdx.y * 128;
    const int n0 = blockIdx.x * 128;
    const int wid = tid >> 5;
    const int wm = wid >> 1;        // 0..3  (32-row band)
    const int wn = wid & 1;         // 0..1  (64-col band)

    wmma::fragment<wmma::accumulator, 16, 16, 16, float> acc[2][4];
#pragma unroll
    for (int i = 0; i < 2; i++)
#pragma unroll
        for (int j = 0; j < 4; j++) wmma::fill_fragment(acc[i][j], 0.f);

    const __half* gsrc[2];
    gsrc[0] = A + (size_t)m0 * K;
    gsrc[1] = W + (size_t)n0 * K;
    const int lr  = tid >> 2;            // row 0..63 (and +64)
    const int lc8 = (tid & 3) * 8;       // col 0/8/16/24

#define H_LOAD(dst4, kc) { \
    _Pragma("unroll") \
    for (int mtx = 0; mtx < 2; mtx++) \
        _Pragma("unroll") \
        for (int t = 0; t < 2; t++) \
            dst4[mtx][t] = *(const uint4*)(gsrc[mtx] + (size_t)(lr + t*64)*K + (kc) + lc8); }

#define H_STORE(bufbase, src4) { \
    _Pragma("unroll") \
    for (int mtx = 0; mtx < 2; mtx++) \
        _Pragma("unroll") \
        for (int t = 0; t < 2; t++) \
            *(uint4*)(bufbase + mtx*MATH_ + (lr + t*64)*LDH + lc8) = src4[mtx][t]; }

    {
        uint4 v[2][2];
        H_LOAD(v, 0);
        H_STORE(smh, v);
    }
    __syncthreads();

    const int NC = K >> 5;
    for (int c = 0; c < NC; c++) {
        const bool more = (c + 1 < NC);
        uint4 v[2][2];
        if (more) H_LOAD(v, (c + 1) * 32);

        {
            const __half* buf = smh + (size_t)(c & 1) * 2 * MATH_;
            const __half* sA = buf;
            const __half* sW = buf + MATH_;
#pragma unroll
            for (int kf = 0; kf < 2; kf++) {
                const int k0 = kf * 16;
                wmma::fragment<wmma::matrix_a, 16,16,16, __half, wmma::row_major> af[2];
#pragma unroll
                for (int i = 0; i < 2; i++)
                    wmma::load_matrix_sync(af[i], sA + (wm*32 + i*16)*LDH + k0, LDH);
#pragma unroll
                for (int j = 0; j < 4; j++) {
                    wmma::fragment<wmma::matrix_b, 16,16,16, __half, wmma::col_major> bf;
                    wmma::load_matrix_sync(bf, sW + (wn*64 + j*16)*LDH + k0, LDH);
#pragma unroll
                    for (int i = 0; i < 2; i++)
                        wmma::mma_sync(acc[i][j], af[i], bf, acc[i][j]);
                }
            }
        }
        if (more) {
            __half* buf = smh + (size_t)((c + 1) & 1) * 2 * MATH_;
            H_STORE(buf, v);
        }
        __syncthreads();
    }

    // epilogue: stage frags through per-warp smem, add bias, scale, store
    float* ep = (float*)smh + wid * (16*20);
    const int lane = tid & 31;
#pragma unroll
    for (int i = 0; i < 2; i++) {
#pragma unroll
        for (int j = 0; j < 4; j++) {
            wmma::store_matrix_sync(ep, acc[i][j], 20, wmma::mem_row_major);
            __syncwarp();
#pragma unroll
            for (int e = 0; e < 8; e++) {
                int idx = lane * 8 + e;
                int r = idx >> 4, cc = idx & 15;
                int m = m0 + wm*32 + i*16 + r;
                int n = n0 + wn*64 + j*16 + cc;
                float v = (ep[r*20 + cc] + bias[n]) * scale;
                if (OMODE == 0) {
                    C[(size_t)m * N + n] = v;
                } else {
                    Cf[(size_t)m * N + n] = __float2half_rn(v);
                }
            }
            __syncwarp();
        }
    }
}

// ---------------------------------------------------------------------------
// Flash attention, fp16 single-term, 512 threads = 16 warps. (R8/R10 proven)
// Output: fp16 AO.
// ---------------------------------------------------------------------------
#define LDQ 72
#define LDK 72
#define LDSF 136
#define OFF_Q  0
#define OFF_K  9216
#define OFF_V  27648
#define OFF_S  46080
#define OFF_L  80896
#define FL_SMEM 81152

__global__ __launch_bounds__(512) void flash_f16(
    const __half* __restrict__ Qf, const __half* __restrict__ Kf,
    const __half* __restrict__ Vf, const float* __restrict__ mask,
    __half* __restrict__ AOf)
{
    extern __shared__ char smraw[];
    __half* sQ = (__half*)(smraw + OFF_Q);
    __half* sK = (__half*)(smraw + OFF_K);
    __half* sV = (__half*)(smraw + OFF_V);
    float*  sS = (float*)(smraw + OFF_S);
    __half* sP = (__half*)(smraw + OFF_S);
    float*  sO = (float*)(smraw + OFF_S);
    float*  sL = (float*)(smraw + OFF_L);

    const int tid = threadIdx.x;
    const int t0 = blockIdx.x * 64;
    const int h  = blockIdx.y;
    const int b  = blockIdx.z;
    const int wid = tid >> 5;
    const int wm = wid >> 3, wn = wid & 7;
    const int wm2 = wid >> 2, wn2 = wid & 3;
    const int srow = tid >> 3;
    const int sc   = (tid & 7) * 16;

    {
        const __half* q = Qf + ((size_t)(b*TT + t0)) * EE + h*HD;
        int r = tid >> 3, c8 = (tid & 7) * 8;
        *(uint4*)&sQ[r*LDQ + c8] = *(const uint4*)(q + (size_t)r*EE + c8);
        if (tid < 64) sL[tid] = 0.f;
    }

    wmma::fragment<wmma::accumulator, 16, 16, 16, float> oacc;
    wmma::fill_fragment(oacc, 0.f);

    const __half* kb = Kf + (size_t)b * SS * EE + h*HD;
    const __half* vb = Vf + (size_t)b * SS * EE + h*HD;
    const float* mrow = mask + ((size_t)(b*TT + t0 + srow)) * TT + sc;

    for (int st = 0; st < SS/128; st++) {
        const int sb = st * 128;
        const int s0b = sb & (TT - 1);

        __syncthreads();
#pragma unroll
        for (int t = 0; t < 2; t++) {
            int slot = tid + t*512;
            int r = slot >> 3, c8 = (slot & 7) * 8;
            size_t go = (size_t)(sb + r) * EE + c8;
            *(uint4*)&sK[r*LDK + c8] = *(const uint4*)(kb + go);
            *(uint4*)&sV[r*LDK + c8] = *(const uint4*)(vb + go);
        }
        __syncthreads();

        {
            wmma::fragment<wmma::accumulator, 16, 16, 16, float> sacc[2];
            wmma::fill_fragment(sacc[0], 0.f);
            wmma::fill_fragment(sacc[1], 0.f);
#pragma unroll
            for (int k = 0; k < 4; k++) {
                wmma::fragment<wmma::matrix_a, 16,16,16, __half, wmma::row_major> af[2];
                wmma::fragment<wmma::matrix_b, 16,16,16, __half, wmma::col_major> bf;
#pragma unroll
                for (int i = 0; i < 2; i++)
                    wmma::load_matrix_sync(af[i], sQ + (wm*32 + i*16)*LDQ + k*16, LDQ);
                wmma::load_matrix_sync(bf, sK + (wn*16)*LDK + k*16, LDK);
#pragma unroll
                for (int i = 0; i < 2; i++)
                    wmma::mma_sync(sacc[i], af[i], bf, sacc[i]);
            }
#pragma unroll
            for (int i = 0; i < 2; i++)
                wmma::store_matrix_sync(sS + (wm*32 + i*16)*LDSF + wn*16,
                                        sacc[i], LDSF, wmma::mem_row_major);
        }
        __syncthreads();

        {
            float p[16];
            const float* mr = mrow + s0b;
            float ls = 0.f;
#pragma unroll
            for (int jv = 0; jv < 4; jv++) {
                float4 mv = *(const float4*)(mr + jv*4);
                float e0 = __expf(sS[srow*LDSF + sc + jv*4 + 0] + mv.x);
                float e1 = __expf(sS[srow*LDSF + sc + jv*4 + 1] + mv.y);
                float e2 = __expf(sS[srow*LDSF + sc + jv*4 + 2] + mv.z);
                float e3 = __expf(sS[srow*LDSF + sc + jv*4 + 3] + mv.w);
                p[jv*4+0] = e0; p[jv*4+1] = e1; p[jv*4+2] = e2; p[jv*4+3] = e3;
                ls += e0 + e1 + e2 + e3;
            }
            ls += __shfl_xor_sync(0xffffffffu, ls, 1);
            ls += __shfl_xor_sync(0xffffffffu, ls, 2);
            ls += __shfl_xor_sync(0xffffffffu, ls, 4);
            __syncthreads();
#pragma unroll
            for (int k2 = 0; k2 < 8; k2++) {
                __half2 pr = __floats2half2_rn(p[2*k2], p[2*k2+1]);
                *(__half2*)&sP[srow*LDSF + sc + 2*k2] = pr;
            }
            if ((tid & 7) == 0) sL[srow] += ls;
        }
        __syncthreads();

#pragma unroll
        for (int k = 0; k < 8; k++) {
            wmma::fragment<wmma::matrix_b, 16,16,16, __half, wmma::row_major> vf;
            wmma::load_matrix_sync(vf, sV + (k*16)*LDK + wn2*16, LDK);
            wmma::fragment<wmma::matrix_a, 16,16,16, __half, wmma::row_major> pf;
            wmma::load_matrix_sync(pf, sP + (wm2*16)*LDSF + k*16, LDSF);
            wmma::mma_sync(oacc, pf, vf, oacc);
        }
    }

    __syncthreads();
    wmma::store_matrix_sync(sO + (wm2*16)*LDQ + wn2*16, oacc, LDQ, wmma::mem_row_major);
    __syncthreads();

    // write out fp16: AO[b, t0+r, h*HD + c] = sO / l
    {
        const int r = tid >> 3;
        const int c8 = (tid & 7) * 8;
        const float inv = 1.f / sL[r];
        __half* ob = AOf + ((size_t)(b*TT + t0 + r)) * EE + h*HD + c8;
#pragma unroll
        for (int v = 0; v < 2; v++) {
            float4 o = *(const float4*)&sO[r*LDQ + c8 + v*4];
            __half2 p0 = __floats2half2_rn(o.x*inv, o.y*inv);
            __half2 p1 = __floats2half2_rn(o.z*inv, o.w*inv);
            *(__half2*)(ob + v*4)     = p0;
            *(__half2*)(ob + v*4 + 2) = p1;
        }
    }
}

// ---------------------------------------------------------------------------
extern "C" void kernel_launch(void* const* d_in, const int* in_sizes, int n_in,
                              void* d_out, int out_size) {
    const float* x    = (const float*)d_in[0];
    const float* mask = (const float*)d_in[1];
    const float* Wq   = (const float*)d_in[2];
    const float* bq   = (const float*)d_in[3];
    const float* Wk   = (const float*)d_in[4];
    const float* bk   = (const float*)d_in[5];
    const float* Wv   = (const float*)d_in[6];
    const float* bv   = (const float*)d_in[7];
    const float* Wo   = (const float*)d_in[8];
    const float* bo   = (const float*)d_in[9];
    float* out = (float*)d_out;

    __half *xf, *Wqf, *Wkf, *Wvf, *Wof, *Qfp, *Kfp, *Vfp, *AOfp;
    cudaGetSymbolAddress((void**)&xf, g_xf);
    cudaGetSymbolAddress((void**)&Wqf, g_Wqf);
    cudaGetSymbolAddress((void**)&Wkf, g_Wkf);
    cudaGetSymbolAddress((void**)&Wvf, g_Wvf);
    cudaGetSymbolAddress((void**)&Wof, g_Wof);
    cudaGetSymbolAddress((void**)&Qfp, g_Qf);
    cudaGetSymbolAddress((void**)&Kfp, g_Kf);
    cudaGetSymbolAddress((void**)&Vfp, g_Vf);
    cudaGetSymbolAddress((void**)&AOfp, g_AOf);

    static bool attr_done = false;
    if (!attr_done) {
        cudaFuncSetAttribute(sgemm_f16<0>, cudaFuncAttributeMaxDynamicSharedMemorySize, SH_SMEM);
        cudaFuncSetAttribute(sgemm_f16<2>, cudaFuncAttributeMaxDynamicSharedMemorySize, SH_SMEM);
        cudaFuncSetAttribute(flash_f16, cudaFuncAttributeMaxDynamicSharedMemorySize, FL_SMEM);
        attr_done = true;
    }

    // 1) convert inputs to fp16
    {
        int nx = BB*TT*EE/4;
        cvt_f16<<<(nx+255)/256, 256>>>(x, xf, nx);
        int nw1 = EE*EE/4;
        cvt_f16<<<(nw1+255)/256, 256>>>(Wq, Wqf, nw1);
        cvt_f16<<<(nw1+255)/256, 256>>>(Wo, Wof, nw1);
        int nw2 = MULT*EE*EE/4;
        cvt_f16<<<(nw2+255)/256, 256>>>(Wk, Wkf, nw2);
        cvt_f16<<<(nw2+255)/256, 256>>>(Wv, Wvf, nw2);
    }

    dim3 gblk(256);
    // 2) QKV projections (fp16 single-term GEMMs)
    sgemm_f16<2><<<dim3(EE/128, (BB*TT)/128), gblk, SH_SMEM>>>(
        xf, Wqf, bq, nullptr, Qfp, EE, EE, QSCALE);
    sgemm_f16<2><<<dim3((MULT*EE)/128, (BB*TT)/128), gblk, SH_SMEM>>>(
        xf, Wkf, bk, nullptr, Kfp, MULT*EE, EE, 1.f);
    sgemm_f16<2><<<dim3((MULT*EE)/128, (BB*TT)/128), gblk, SH_SMEM>>>(
        xf, Wvf, bv, nullptr, Vfp, MULT*EE, EE, 1.f);
    // 3) flash attention (fp16 single) -> fp16 AO
    flash_f16<<<dim3(TT/64, HH, BB), dim3(512), FL_SMEM>>>(
        Qfp, Kfp, Vfp, mask, AOfp);
    // 4) output projection (fp16 single-term, fp32 out)
    sgemm_f16<0><<<dim3(EE/128, (BB*TT)/128), gblk, SH_SMEM>>>(
        AOfp, Wof, bo, out, nullptr, EE, EE, 1.f);
}